// round 10
// baseline (speedup 1.0000x reference)
#include <cuda_runtime.h>

#define B_ 8
#define P_ 10
#define S_ 160
#define FX_ 11
#define D_ 64
#define DFF_ 256
#define NROW (B_*P_*S_)   /* 12800 */
#define NPART (B_*P_)     /* 80 */
#define NTILE (NROW/32)   /* 400 */

/* output layout (tuple order): pred, pred_resampl, K, V, R, attn_weights */
#define OFF_PRED  0
#define OFF_PRED2 (NROW)
#define OFF_K     (2*NROW)
#define OFF_V     (OFF_K + NROW*D_)
#define OFF_R     (OFF_V + NROW*D_)
#define OFF_ATTN  (OFF_R + NROW*D_)

/* scratch (no cudaMalloc allowed) */
__device__ float g_x[NROW*D_];
__device__ float g_q[NROW*D_];
__device__ float g_z[NROW*D_];
__device__ float g_o1[NROW*D_];     /* post-LN1 activations */
__device__ float g_h[NROW*DFF_];    /* FFN1 output (13 MB, L2-resident) */
__device__ float g_fw[4*704];
__device__ float g_fb[4*64];
__device__ int   g_ctrA;
__device__ int   g_ctrB;

__device__ __forceinline__ void fma4(float4& acc, float s, const float4& v) {
    acc.x += s * v.x; acc.y += s * v.y; acc.z += s * v.z; acc.w += s * v.w;
}

/* ------------------------------------------------------------------ */
/* K0: fold Wp into Wq/Wk/Wv (+ reset tile queues).                   */
/* ------------------------------------------------------------------ */
__global__ void __launch_bounds__(256) k_fold(
    const float* __restrict__ Wp, const float* __restrict__ bp,
    const float* __restrict__ Wq, const float* __restrict__ bq,
    const float* __restrict__ Wk, const float* __restrict__ bk,
    const float* __restrict__ Wv, const float* __restrict__ bv)
{
    __shared__ float sWp[704];
    __shared__ float sW[4096];
    const int b = blockIdx.x, tid = threadIdx.x;
    if (b == 0) {
        if (tid == 0) { g_ctrA = 0; g_ctrB = 0; }
        for (int i = tid; i < 704; i += 256) g_fw[i] = 8.0f * Wp[i];
        if (tid < 64) g_fb[tid] = 8.0f * bp[tid];
        return;
    }
    const float* W  = (b == 1) ? Wq : (b == 2) ? Wk : Wv;
    const float* bb = (b == 1) ? bq : (b == 2) ? bk : bv;
    const float fw = (b == 1) ? 1.0f   : 8.0f;
    const float fb = (b == 1) ? 0.125f : 1.0f;
    for (int i = tid; i < 704;  i += 256) sWp[i] = Wp[i];
    for (int i = tid; i < 4096; i += 256) sW[i]  = W[i];
    __syncthreads();
    const int j = tid & 63, g = tid >> 6;
    for (int i = g; i < 11; i += 4) {
        float s = 0.0f;
        #pragma unroll 4
        for (int d = 0; d < 64; ++d) s += sWp[i*64 + d] * sW[d*64 + j];
        g_fw[b*704 + i*64 + j] = fw * s;
    }
    if (tid < 64) {
        float s = 0.0f;
        for (int d = 0; d < 64; ++d) s += bp[d] * sW[d*64 + tid];
        g_fb[b*64 + tid] = fw * s + fb * bb[tid];
    }
}

/* ------------------------------------------------------------------ */
/* K1: x,q,k,v = in @ fused.                                          */
/* ------------------------------------------------------------------ */
__global__ void __launch_bounds__(512) k_qkv(
    const float* __restrict__ inp,
    float* __restrict__ outK, float* __restrict__ outV)
{
    extern __shared__ float sm[];
    float* sW  = sm;
    float* sB  = sW + 2816;
    float* sIn = sB + 256;
    const int tid = threadIdx.x;
    const int row0 = blockIdx.x * 64;

    for (int i = tid; i < 2816; i += 512) sW[i] = g_fw[i];
    if (tid < 256) sB[tid] = g_fb[tid];
    for (int i = tid; i < 704; i += 512) sIn[i] = inp[(size_t)row0*11 + i];
    __syncthreads();

    const int j = tid & 63, rb = (tid >> 6) * 8;
    float wx[11], wq[11], wk[11], wv[11];
    #pragma unroll
    for (int i = 0; i < 11; ++i) {
        wx[i] = sW[i*64 + j];
        wq[i] = sW[704  + i*64 + j];
        wk[i] = sW[1408 + i*64 + j];
        wv[i] = sW[2112 + i*64 + j];
    }
    float ax[8], aq[8], ak[8], av[8];
    #pragma unroll
    for (int r = 0; r < 8; ++r) {
        ax[r] = sB[j]; aq[r] = sB[64+j]; ak[r] = sB[128+j]; av[r] = sB[192+j];
    }
    #pragma unroll
    for (int i = 0; i < 11; ++i) {
        #pragma unroll
        for (int r = 0; r < 8; ++r) {
            float in = sIn[(rb+r)*11 + i];
            ax[r] += in * wx[i];
            aq[r] += in * wq[i];
            ak[r] += in * wk[i];
            av[r] += in * wv[i];
        }
    }
    #pragma unroll
    for (int r = 0; r < 8; ++r) {
        size_t n = (size_t)(row0 + rb + r) * 64 + j;
        g_x[n]  = ax[r];
        g_q[n]  = aq[r];
        outK[n] = ak[r];
        outV[n] = av[r];
    }
}

/* ------------------------------------------------------------------ */
/* K2: causal attention (unchanged).                                  */
/* ------------------------------------------------------------------ */
template<int NC>
__device__ __forceinline__ void score_nc(
    const float* __restrict__ sKt, const float* __restrict__ sQ,
    int mbase, int lane, float (&sc)[5][5])
{
    #pragma unroll 2
    for (int i = 0; i < 64; ++i) {
        float kv[NC];
        #pragma unroll
        for (int c = 0; c < NC; ++c) kv[c] = sKt[i*161 + c*32 + lane];
        #pragma unroll
        for (int k = 0; k < 5; ++k) {
            float qi = sQ[(mbase+k)*64 + i];
            #pragma unroll
            for (int c = 0; c < NC; ++c) sc[k][c] += qi * kv[c];
        }
    }
}

__global__ void __launch_bounds__(256) k_attn(
    const float* __restrict__ Kin, const float* __restrict__ Vin,
    float* __restrict__ attnOut)
{
    extern __shared__ float sm[];
    float* sKt = sm;
    float* sV  = sKt + 10304;
    float* sQ  = sV  + 10240;
    float* sA  = sKt;

    const int tid  = threadIdx.x;
    const int lane = tid & 31;
    const int w    = tid >> 5;
    const int part = blockIdx.x >> 2;
    const int quad = blockIdx.x & 3;
    const int r    = (w < 4) ? w : 11 - w;
    const int mbase = 5 * r;
    const int tmax  = quad + 20*r + 16;
    const int nc    = (tmax >> 5) + 1;

    const float4* Kg4 = (const float4*)(Kin + (size_t)part*160*64);
    const float4* Vg4 = (const float4*)(Vin + (size_t)part*160*64);
    float4* sV4 = (float4*)sV;

    for (int idx = tid; idx < 160*16; idx += 256) {
        int s = idx >> 4, i4 = (idx & 15) * 4;
        float4 kk = Kg4[idx];
        sKt[(i4+0)*161 + s] = kk.x;
        sKt[(i4+1)*161 + s] = kk.y;
        sKt[(i4+2)*161 + s] = kk.z;
        sKt[(i4+3)*161 + s] = kk.w;
        sV4[idx] = Vg4[idx];
    }
    for (int idx = tid; idx < 40*16; idx += 256) {
        int m = idx >> 4, i4 = idx & 15;
        int row = part*160 + quad + 4*m;
        ((float4*)(sQ + m*64))[i4] = ((const float4*)(g_q + (size_t)row*64))[i4];
    }
    __syncthreads();

    float sc[5][5];
    #pragma unroll
    for (int k = 0; k < 5; ++k)
        #pragma unroll
        for (int c = 0; c < 5; ++c) sc[k][c] = 0.0f;

    switch (nc) {
        case 1: score_nc<1>(sKt, sQ, mbase, lane, sc); break;
        case 2: score_nc<2>(sKt, sQ, mbase, lane, sc); break;
        case 3: score_nc<3>(sKt, sQ, mbase, lane, sc); break;
        case 4: score_nc<4>(sKt, sQ, mbase, lane, sc); break;
        default: score_nc<5>(sKt, sQ, mbase, lane, sc); break;
    }

    #pragma unroll
    for (int k = 0; k < 5; ++k) {
        const int t = quad + 4*(mbase + k);
        float mval = -3.4e38f;
        #pragma unroll
        for (int c = 0; c < 5; ++c) {
            int s = c*32 + lane;
            if (c < nc && s <= t) mval = fmaxf(mval, sc[k][c]);
        }
        #pragma unroll
        for (int o = 16; o; o >>= 1) mval = fmaxf(mval, __shfl_xor_sync(0xffffffffu, mval, o));
        float sum = 0.0f;
        #pragma unroll
        for (int c = 0; c < 5; ++c) {
            int s = c*32 + lane;
            float p = (c < nc && s <= t) ? expf(sc[k][c] - mval) : 0.0f;
            sc[k][c] = p;
            sum += p;
        }
        #pragma unroll
        for (int o = 16; o; o >>= 1) sum += __shfl_xor_sync(0xffffffffu, sum, o);
        float inv = 1.0f / sum;
        float* arow = attnOut + (size_t)(part*160 + t)*160;
        #pragma unroll
        for (int c = 0; c < 5; ++c) {
            if (c < nc) {
                sc[k][c] *= inv;
                arow[c*32 + lane] = sc[k][c];
            } else {
                arow[c*32 + lane] = 0.0f;
            }
        }
    }

    __syncthreads();

    #pragma unroll
    for (int k = 0; k < 5; ++k) {
        #pragma unroll
        for (int c = 0; c < 5; ++c)
            if (c < nc) sA[(mbase+k)*160 + c*32 + lane] = sc[k][c];
    }
    __syncwarp();

    const float2* sV2 = (const float2*)sV;
    float2 acc[5];
    #pragma unroll
    for (int k = 0; k < 5; ++k) acc[k] = make_float2(0.f, 0.f);

    const int send = (tmax + 4) & ~3;
    for (int s = 0; s < send; s += 4) {
        float4 a[5];
        #pragma unroll
        for (int k = 0; k < 5; ++k)
            a[k] = *(const float4*)(sA + (mbase+k)*160 + s);
        float2 v0 = sV2[(s+0)*32 + lane];
        float2 v1 = sV2[(s+1)*32 + lane];
        float2 v2 = sV2[(s+2)*32 + lane];
        float2 v3 = sV2[(s+3)*32 + lane];
        #pragma unroll
        for (int k = 0; k < 5; ++k) {
            acc[k].x += a[k].x*v0.x + a[k].y*v1.x + a[k].z*v2.x + a[k].w*v3.x;
            acc[k].y += a[k].x*v0.y + a[k].y*v1.y + a[k].z*v2.y + a[k].w*v3.y;
        }
    }
    #pragma unroll
    for (int k = 0; k < 5; ++k) {
        const int t = quad + 4*(mbase + k);
        size_t n = (size_t)part*160 + t;
        ((float2*)(g_z + n*64))[lane] = acc[k];
    }
}

/* ------------------------------------------------------------------ */
/* K3a: Wo + LN1 + FFN1 (relu) -> g_h, g_o1.  ~108.6 KB smem, 2/SM.   */
/* Dynamic tile queue; 32-row tiles; R5 FFMA float4 stages.           */
/* ------------------------------------------------------------------ */
__global__ void __launch_bounds__(512) k_epiA(
    const float* __restrict__ Wo, const float* __restrict__ bo,
    const float* __restrict__ ln1g, const float* __restrict__ ln1b,
    const float* __restrict__ W1, const float* __restrict__ b1)
{
    extern __shared__ float sm[];
    float* sWo = sm;            /* 4096  */
    float* sW1 = sWo + 4096;    /* 16384 */
    float* sC  = sW1 + 16384;   /* 512: bo | b1 | l1g | l1b */
    float* sO1 = sC  + 512;     /* 2048 */
    float* sP  = sO1 + 2048;    /* 2 x 2048 Wo partials */
    int*   sT  = (int*)(sP + 4096);

    const int tid = threadIdx.x;
    for (int i = tid; i < 1024; i += 512) ((float4*)sWo)[i] = ((const float4*)Wo)[i];
    for (int i = tid; i < 4096; i += 512) ((float4*)sW1)[i] = ((const float4*)W1)[i];
    if (tid < 64) {
        sC[tid]     = bo[tid];
        sC[320+tid] = ln1g[tid];
        sC[384+tid] = ln1b[tid];
    }
    if (tid < 256) sC[64 + tid] = b1[tid];

    const int isp = tid >> 8;          /* 0..1 K-split for Wo */
    const int t1  = tid & 255;
    const int cq1 = t1 & 15;           /* Wo col-quad (cols 4cq1..) */
    const int rq1 = t1 >> 4;           /* 0..15 -> rows 2rq1.. */
    const int rw  = tid >> 4;          /* 0..31 */
    const int c4  = tid & 15;
    const int cqf = tid & 63;          /* FFN1 col-quad */
    const int rqf = tid >> 6;          /* 0..7 -> rows 4rqf.. */

    for (;;) {
        if (tid == 0) sT[0] = atomicAdd(&g_ctrA, 1);
        __syncthreads();
        const int tile = sT[0];
        if (tile >= NTILE) break;
        const int row0 = tile * 32;

        /* S1: Wo, 2-way K-split, 2 rows x 4 cols */
        {
            float4 acc0 = {0,0,0,0}, acc1 = {0,0,0,0};
            #pragma unroll
            for (int i4 = isp*8; i4 < isp*8 + 8; ++i4) {
                float4 w0 = ((const float4*)(sWo + (i4*4+0)*64))[cq1];
                float4 w1 = ((const float4*)(sWo + (i4*4+1)*64))[cq1];
                float4 w2 = ((const float4*)(sWo + (i4*4+2)*64))[cq1];
                float4 w3 = ((const float4*)(sWo + (i4*4+3)*64))[cq1];
                float4 a0 = ((const float4*)(g_z + (size_t)(row0 + 2*rq1+0)*64))[i4];
                float4 a1 = ((const float4*)(g_z + (size_t)(row0 + 2*rq1+1)*64))[i4];
                fma4(acc0, a0.x, w0); fma4(acc0, a0.y, w1); fma4(acc0, a0.z, w2); fma4(acc0, a0.w, w3);
                fma4(acc1, a1.x, w0); fma4(acc1, a1.y, w1); fma4(acc1, a1.z, w2); fma4(acc1, a1.w, w3);
            }
            float4* dst = (float4*)(sP + isp*2048);
            dst[(2*rq1+0)*16 + cq1] = acc0;
            dst[(2*rq1+1)*16 + cq1] = acc1;
        }
        __syncthreads();

        /* S2: reduce + bias + residual + LN1 -> sO1, g_o1 */
        {
            const float4* p = (const float4*)sP;
            float4 v  = p[tid];
            float4 v1 = p[512 + tid];
            float4 b  = ((const float4*)sC)[c4];
            float4 rx = ((const float4*)(g_x + (size_t)(row0 + rw)*64))[c4];
            v.x += v1.x + b.x + rx.x;
            v.y += v1.y + b.y + rx.y;
            v.z += v1.z + b.z + rx.z;
            v.w += v1.w + b.w + rx.w;
            float s = v.x + v.y + v.z + v.w;
            #pragma unroll
            for (int o = 8; o; o >>= 1) s += __shfl_xor_sync(0xffffffffu, s, o);
            float mu = s * (1.0f/64.0f);
            float4 d = {v.x-mu, v.y-mu, v.z-mu, v.w-mu};
            float q = d.x*d.x + d.y*d.y + d.z*d.z + d.w*d.w;
            #pragma unroll
            for (int o = 8; o; o >>= 1) q += __shfl_xor_sync(0xffffffffu, q, o);
            float is = rsqrtf(q * (1.0f/64.0f) + 1e-6f);
            float4 g  = ((const float4*)(sC + 320))[c4];
            float4 bb = ((const float4*)(sC + 384))[c4];
            float4 o1 = {g.x*d.x*is + bb.x, g.y*d.y*is + bb.y,
                         g.z*d.z*is + bb.z, g.w*d.w*is + bb.w};
            ((float4*)sO1)[tid] = o1;
            ((float4*)(g_o1 + (size_t)(row0 + rw)*64))[c4] = o1;
        }
        __syncthreads();

        /* S3: FFN1 4x4 + relu -> g_h */
        {
            float4 b = ((const float4*)(sC + 64))[cqf];
            float4 acc0 = b, acc1 = b, acc2 = b, acc3 = b;
            #pragma unroll 4
            for (int i4 = 0; i4 < 16; ++i4) {
                float4 w0 = ((const float4*)(sW1 + (i4*4+0)*256))[cqf];
                float4 w1 = ((const float4*)(sW1 + (i4*4+1)*256))[cqf];
                float4 w2 = ((const float4*)(sW1 + (i4*4+2)*256))[cqf];
                float4 w3 = ((const float4*)(sW1 + (i4*4+3)*256))[cqf];
                float4 a0 = ((const float4*)(sO1 + (4*rqf+0)*64))[i4];
                float4 a1 = ((const float4*)(sO1 + (4*rqf+1)*64))[i4];
                float4 a2 = ((const float4*)(sO1 + (4*rqf+2)*64))[i4];
                float4 a3 = ((const float4*)(sO1 + (4*rqf+3)*64))[i4];
                fma4(acc0, a0.x, w0); fma4(acc0, a0.y, w1); fma4(acc0, a0.z, w2); fma4(acc0, a0.w, w3);
                fma4(acc1, a1.x, w0); fma4(acc1, a1.y, w1); fma4(acc1, a1.z, w2); fma4(acc1, a1.w, w3);
                fma4(acc2, a2.x, w0); fma4(acc2, a2.y, w1); fma4(acc2, a2.z, w2); fma4(acc2, a2.w, w3);
                fma4(acc3, a3.x, w0); fma4(acc3, a3.y, w1); fma4(acc3, a3.z, w2); fma4(acc3, a3.w, w3);
            }
            acc0.x = fmaxf(acc0.x, 0.f); acc0.y = fmaxf(acc0.y, 0.f);
            acc0.z = fmaxf(acc0.z, 0.f); acc0.w = fmaxf(acc0.w, 0.f);
            acc1.x = fmaxf(acc1.x, 0.f); acc1.y = fmaxf(acc1.y, 0.f);
            acc1.z = fmaxf(acc1.z, 0.f); acc1.w = fmaxf(acc1.w, 0.f);
            acc2.x = fmaxf(acc2.x, 0.f); acc2.y = fmaxf(acc2.y, 0.f);
            acc2.z = fmaxf(acc2.z, 0.f); acc2.w = fmaxf(acc2.w, 0.f);
            acc3.x = fmaxf(acc3.x, 0.f); acc3.y = fmaxf(acc3.y, 0.f);
            acc3.z = fmaxf(acc3.z, 0.f); acc3.w = fmaxf(acc3.w, 0.f);
            ((float4*)(g_h + (size_t)(row0 + 4*rqf+0)*256))[cqf] = acc0;
            ((float4*)(g_h + (size_t)(row0 + 4*rqf+1)*256))[cqf] = acc1;
            ((float4*)(g_h + (size_t)(row0 + 4*rqf+2)*256))[cqf] = acc2;
            ((float4*)(g_h + (size_t)(row0 + 4*rqf+3)*256))[cqf] = acc3;
        }
        __syncthreads();
    }
}

/* ------------------------------------------------------------------ */
/* K3b: FFN2 + LN2 + outputs.  ~83 KB smem, 2/SM.                     */
/* ------------------------------------------------------------------ */
__global__ void __launch_bounds__(512) k_epiB(
    const float* __restrict__ W2, const float* __restrict__ b2,
    const float* __restrict__ ln2g, const float* __restrict__ ln2b,
    const float* __restrict__ Wf, const float* __restrict__ bf,
    float* __restrict__ outR, float* __restrict__ outP, float* __restrict__ outP2)
{
    extern __shared__ float sm[];
    float* sW2 = sm;            /* 16384 */
    float* sC  = sW2 + 16384;   /* 256: b2 | l2g | l2b | wf */
    float* sP  = sC + 256;      /* 2 x 2048 partials */
    int*   sT  = (int*)(sP + 4096);

    const int tid = threadIdx.x;
    for (int i = tid; i < 4096; i += 512) ((float4*)sW2)[i] = ((const float4*)W2)[i];
    if (tid < 64) {
        sC[tid]     = b2[tid];
        sC[64+tid]  = ln2g[tid];
        sC[128+tid] = ln2b[tid];
        sC[192+tid] = Wf[tid];
    }
    const float bfv = bf[0];

    const int isp = tid >> 8;          /* 0..1 K-split */
    const int t1  = tid & 255;
    const int cq  = t1 & 15;           /* cols 4cq.. */
    const int rq  = t1 >> 4;           /* 0..15 -> rows 2rq.. */
    const int rw  = tid >> 4;
    const int c4  = tid & 15;

    for (;;) {
        if (tid == 0) sT[0] = atomicAdd(&g_ctrB, 1);
        __syncthreads();
        const int tile = sT[0];
        if (tile >= NTILE) break;
        const int row0 = tile * 32;

        /* S4: FFN2, 2-way K-split (128 each), 2 rows x 4 cols */
        {
            float4 acc0 = {0,0,0,0}, acc1 = {0,0,0,0};
            #pragma unroll 4
            for (int i4 = isp*32; i4 < isp*32 + 32; ++i4) {
                float4 w0 = ((const float4*)(sW2 + (i4*4+0)*64))[cq];
                float4 w1 = ((const float4*)(sW2 + (i4*4+1)*64))[cq];
                float4 w2 = ((const float4*)(sW2 + (i4*4+2)*64))[cq];
                float4 w3 = ((const float4*)(sW2 + (i4*4+3)*64))[cq];
                float4 a0 = ((const float4*)(g_h + (size_t)(row0 + 2*rq+0)*256))[i4];
                float4 a1 = ((const float4*)(g_h + (size_t)(row0 + 2*rq+1)*256))[i4];
                fma4(acc0, a0.x, w0); fma4(acc0, a0.y, w1); fma4(acc0, a0.z, w2); fma4(acc0, a0.w, w3);
                fma4(acc1, a1.x, w0); fma4(acc1, a1.y, w1); fma4(acc1, a1.z, w2); fma4(acc1, a1.w, w3);
            }
            float4* dst = (float4*)(sP + isp*2048);
            dst[(2*rq+0)*16 + cq] = acc0;
            dst[(2*rq+1)*16 + cq] = acc1;
        }
        __syncthreads();

        /* S5: reduce + bias + residual + LN2 + outputs */
        {
            const float4* p = (const float4*)sP;
            float4 v  = p[tid];
            float4 v1 = p[512 + tid];
            float4 b  = ((const float4*)sC)[c4];
            float4 rs = ((const float4*)(g_o1 + (size_t)(row0 + rw)*64))[c4];
            v.x += v1.x + b.x + rs.x;
            v.y += v1.y + b.y + rs.y;
            v.z += v1.z + b.z + rs.z;
            v.w += v1.w + b.w + rs.w;
            float s = v.x + v.y + v.z + v.w;
            #pragma unroll
            for (int o = 8; o; o >>= 1) s += __shfl_xor_sync(0xffffffffu, s, o);
            float mu = s * (1.0f/64.0f);
            float4 d = {v.x-mu, v.y-mu, v.z-mu, v.w-mu};
            float q = d.x*d.x + d.y*d.y + d.z*d.z + d.w*d.w;
            #pragma unroll
            for (int o = 8; o; o >>= 1) q += __shfl_xor_sync(0xffffffffu, q, o);
            float is = rsqrtf(q * (1.0f/64.0f) + 1e-6f);
            float4 g  = ((const float4*)(sC + 64))[c4];
            float4 bb = ((const float4*)(sC + 128))[c4];
            float4 rv = {g.x*d.x*is + bb.x, g.y*d.y*is + bb.y,
                         g.z*d.z*is + bb.z, g.w*d.w*is + bb.w};
            const size_t n = (size_t)row0 + rw;
            ((float4*)(outR + n*64))[c4] = rv;
            float4 wf = ((const float4*)(sC + 192))[c4];
            float pp = rv.x*wf.x + rv.y*wf.y + rv.z*wf.z + rv.w*wf.w;
            #pragma unroll
            for (int o = 8; o; o >>= 1) pp += __shfl_xor_sync(0xffffffffu, pp, o);
            if (c4 == 0) {
                float pv = pp + bfv;
                outP[n]  = pv;
                outP2[n] = pv;
            }
        }
        __syncthreads();
    }
}

/* ------------------------------------------------------------------ */
extern "C" void kernel_launch(void* const* d_in, const int* in_sizes, int n_in,
                              void* d_out, int out_size)
{
    (void)in_sizes; (void)n_in; (void)out_size;
    const float* inputs = (const float*)d_in[0];
    const float* Wp  = (const float*)d_in[2];
    const float* bp  = (const float*)d_in[3];
    const float* Wq  = (const float*)d_in[4];
    const float* bq  = (const float*)d_in[5];
    const float* Wk  = (const float*)d_in[6];
    const float* bk  = (const float*)d_in[7];
    const float* Wv  = (const float*)d_in[8];
    const float* bv  = (const float*)d_in[9];
    const float* Wo  = (const float*)d_in[10];
    const float* bo  = (const float*)d_in[11];
    const float* l1g = (const float*)d_in[12];
    const float* l1b = (const float*)d_in[13];
    const float* W1  = (const float*)d_in[14];
    const float* b1  = (const float*)d_in[15];
    const float* W2  = (const float*)d_in[16];
    const float* b2  = (const float*)d_in[17];
    const float* l2g = (const float*)d_in[18];
    const float* l2b = (const float*)d_in[19];
    const float* Wf  = (const float*)d_in[20];
    const float* bf  = (const float*)d_in[21];
    float* out = (float*)d_out;

    const size_t sm1 = (size_t)(2816 + 256 + 704) * 4;                    /* ~15 KB  */
    const size_t sm2 = (size_t)(10304 + 10240 + 2560) * 4;                /* ~92 KB  */
    const size_t smA = (size_t)(4096 + 16384 + 512 + 2048 + 4096 + 4) * 4;/* ~108.6 KB */
    const size_t smB = (size_t)(16384 + 256 + 4096 + 4) * 4;              /* ~83 KB  */

    cudaFuncSetAttribute(k_qkv,  cudaFuncAttributeMaxDynamicSharedMemorySize, (int)sm1);
    cudaFuncSetAttribute(k_attn, cudaFuncAttributeMaxDynamicSharedMemorySize, (int)sm2);
    cudaFuncSetAttribute(k_epiA, cudaFuncAttributeMaxDynamicSharedMemorySize, (int)smA);
    cudaFuncSetAttribute(k_epiB, cudaFuncAttributeMaxDynamicSharedMemorySize, (int)smB);

    k_fold<<<4, 256>>>(Wp, bp, Wq, bq, Wk, bk, Wv, bv);
    k_qkv<<<NROW/64, 512, sm1>>>(inputs, out + OFF_K, out + OFF_V);
    k_attn<<<NPART*4, 256, sm2>>>(out + OFF_K, out + OFF_V, out + OFF_ATTN);
    k_epiA<<<296, 512, smA>>>(Wo, bo, l1g, l1b, W1, b1);
    k_epiB<<<296, 512, smB>>>(W2, b2, l2g, l2b, Wf, bf,
                              out + OFF_R, out + OFF_PRED, out + OFF_PRED2);
}

// round 11
// speedup vs baseline: 1.0966x; 1.0966x over previous
#include <cuda_runtime.h>

#define B_ 8
#define P_ 10
#define S_ 160
#define FX_ 11
#define D_ 64
#define DFF_ 256
#define NROW (B_*P_*S_)   /* 12800 */
#define NPART (B_*P_)     /* 80 */
#define NTILE (NROW/32)   /* 400 */

/* output layout (tuple order): pred, pred_resampl, K, V, R, attn_weights */
#define OFF_PRED  0
#define OFF_PRED2 (NROW)
#define OFF_K     (2*NROW)
#define OFF_V     (OFF_K + NROW*D_)
#define OFF_R     (OFF_V + NROW*D_)
#define OFF_ATTN  (OFF_R + NROW*D_)

/* scratch (no cudaMalloc allowed) */
__device__ float g_x[NROW*D_];
__device__ float g_q[NROW*D_];
__device__ float g_z[NROW*D_];
__device__ float g_fw[4*704];
__device__ float g_fb[4*64];
__device__ int   g_ctrA;

__device__ __forceinline__ void fma4(float4& acc, float s, const float4& v) {
    acc.x += s * v.x; acc.y += s * v.y; acc.z += s * v.z; acc.w += s * v.w;
}

/* ------------------------------------------------------------------ */
/* K0: fold Wp into Wq/Wk/Wv (+ reset tile queue).                    */
/* ------------------------------------------------------------------ */
__global__ void __launch_bounds__(256) k_fold(
    const float* __restrict__ Wp, const float* __restrict__ bp,
    const float* __restrict__ Wq, const float* __restrict__ bq,
    const float* __restrict__ Wk, const float* __restrict__ bk,
    const float* __restrict__ Wv, const float* __restrict__ bv)
{
    __shared__ float sWp[704];
    __shared__ float sW[4096];
    const int b = blockIdx.x, tid = threadIdx.x;
    if (b == 0) {
        if (tid == 0) g_ctrA = 0;
        for (int i = tid; i < 704; i += 256) g_fw[i] = 8.0f * Wp[i];
        if (tid < 64) g_fb[tid] = 8.0f * bp[tid];
        return;
    }
    const float* W  = (b == 1) ? Wq : (b == 2) ? Wk : Wv;
    const float* bb = (b == 1) ? bq : (b == 2) ? bk : bv;
    const float fw = (b == 1) ? 1.0f   : 8.0f;
    const float fb = (b == 1) ? 0.125f : 1.0f;
    for (int i = tid; i < 704;  i += 256) sWp[i] = Wp[i];
    for (int i = tid; i < 4096; i += 256) sW[i]  = W[i];
    __syncthreads();
    const int j = tid & 63, g = tid >> 6;
    for (int i = g; i < 11; i += 4) {
        float s = 0.0f;
        #pragma unroll 4
        for (int d = 0; d < 64; ++d) s += sWp[i*64 + d] * sW[d*64 + j];
        g_fw[b*704 + i*64 + j] = fw * s;
    }
    if (tid < 64) {
        float s = 0.0f;
        for (int d = 0; d < 64; ++d) s += bp[d] * sW[d*64 + tid];
        g_fb[b*64 + tid] = fw * s + fb * bb[tid];
    }
}

/* ------------------------------------------------------------------ */
/* K1: x,q,k,v = in @ fused.                                          */
/* ------------------------------------------------------------------ */
__global__ void __launch_bounds__(512) k_qkv(
    const float* __restrict__ inp,
    float* __restrict__ outK, float* __restrict__ outV)
{
    extern __shared__ float sm[];
    float* sW  = sm;
    float* sB  = sW + 2816;
    float* sIn = sB + 256;
    const int tid = threadIdx.x;
    const int row0 = blockIdx.x * 64;

    for (int i = tid; i < 2816; i += 512) sW[i] = g_fw[i];
    if (tid < 256) sB[tid] = g_fb[tid];
    for (int i = tid; i < 704; i += 512) sIn[i] = inp[(size_t)row0*11 + i];
    __syncthreads();

    const int j = tid & 63, rb = (tid >> 6) * 8;
    float wx[11], wq[11], wk[11], wv[11];
    #pragma unroll
    for (int i = 0; i < 11; ++i) {
        wx[i] = sW[i*64 + j];
        wq[i] = sW[704  + i*64 + j];
        wk[i] = sW[1408 + i*64 + j];
        wv[i] = sW[2112 + i*64 + j];
    }
    float ax[8], aq[8], ak[8], av[8];
    #pragma unroll
    for (int r = 0; r < 8; ++r) {
        ax[r] = sB[j]; aq[r] = sB[64+j]; ak[r] = sB[128+j]; av[r] = sB[192+j];
    }
    #pragma unroll
    for (int i = 0; i < 11; ++i) {
        #pragma unroll
        for (int r = 0; r < 8; ++r) {
            float in = sIn[(rb+r)*11 + i];
            ax[r] += in * wx[i];
            aq[r] += in * wq[i];
            ak[r] += in * wk[i];
            av[r] += in * wv[i];
        }
    }
    #pragma unroll
    for (int r = 0; r < 8; ++r) {
        size_t n = (size_t)(row0 + rb + r) * 64 + j;
        g_x[n]  = ax[r];
        g_q[n]  = aq[r];
        outK[n] = ak[r];
        outV[n] = av[r];
    }
}

/* ------------------------------------------------------------------ */
/* K2: causal attention (unchanged).                                  */
/* ------------------------------------------------------------------ */
template<int NC>
__device__ __forceinline__ void score_nc(
    const float* __restrict__ sKt, const float* __restrict__ sQ,
    int mbase, int lane, float (&sc)[5][5])
{
    #pragma unroll 2
    for (int i = 0; i < 64; ++i) {
        float kv[NC];
        #pragma unroll
        for (int c = 0; c < NC; ++c) kv[c] = sKt[i*161 + c*32 + lane];
        #pragma unroll
        for (int k = 0; k < 5; ++k) {
            float qi = sQ[(mbase+k)*64 + i];
            #pragma unroll
            for (int c = 0; c < NC; ++c) sc[k][c] += qi * kv[c];
        }
    }
}

__global__ void __launch_bounds__(256) k_attn(
    const float* __restrict__ Kin, const float* __restrict__ Vin,
    float* __restrict__ attnOut)
{
    extern __shared__ float sm[];
    float* sKt = sm;
    float* sV  = sKt + 10304;
    float* sQ  = sV  + 10240;
    float* sA  = sKt;

    const int tid  = threadIdx.x;
    const int lane = tid & 31;
    const int w    = tid >> 5;
    const int part = blockIdx.x >> 2;
    const int quad = blockIdx.x & 3;
    const int r    = (w < 4) ? w : 11 - w;
    const int mbase = 5 * r;
    const int tmax  = quad + 20*r + 16;
    const int nc    = (tmax >> 5) + 1;

    const float4* Kg4 = (const float4*)(Kin + (size_t)part*160*64);
    const float4* Vg4 = (const float4*)(Vin + (size_t)part*160*64);
    float4* sV4 = (float4*)sV;

    for (int idx = tid; idx < 160*16; idx += 256) {
        int s = idx >> 4, i4 = (idx & 15) * 4;
        float4 kk = Kg4[idx];
        sKt[(i4+0)*161 + s] = kk.x;
        sKt[(i4+1)*161 + s] = kk.y;
        sKt[(i4+2)*161 + s] = kk.z;
        sKt[(i4+3)*161 + s] = kk.w;
        sV4[idx] = Vg4[idx];
    }
    for (int idx = tid; idx < 40*16; idx += 256) {
        int m = idx >> 4, i4 = idx & 15;
        int row = part*160 + quad + 4*m;
        ((float4*)(sQ + m*64))[i4] = ((const float4*)(g_q + (size_t)row*64))[i4];
    }
    __syncthreads();

    float sc[5][5];
    #pragma unroll
    for (int k = 0; k < 5; ++k)
        #pragma unroll
        for (int c = 0; c < 5; ++c) sc[k][c] = 0.0f;

    switch (nc) {
        case 1: score_nc<1>(sKt, sQ, mbase, lane, sc); break;
        case 2: score_nc<2>(sKt, sQ, mbase, lane, sc); break;
        case 3: score_nc<3>(sKt, sQ, mbase, lane, sc); break;
        case 4: score_nc<4>(sKt, sQ, mbase, lane, sc); break;
        default: score_nc<5>(sKt, sQ, mbase, lane, sc); break;
    }

    #pragma unroll
    for (int k = 0; k < 5; ++k) {
        const int t = quad + 4*(mbase + k);
        float mval = -3.4e38f;
        #pragma unroll
        for (int c = 0; c < 5; ++c) {
            int s = c*32 + lane;
            if (c < nc && s <= t) mval = fmaxf(mval, sc[k][c]);
        }
        #pragma unroll
        for (int o = 16; o; o >>= 1) mval = fmaxf(mval, __shfl_xor_sync(0xffffffffu, mval, o));
        float sum = 0.0f;
        #pragma unroll
        for (int c = 0; c < 5; ++c) {
            int s = c*32 + lane;
            float p = (c < nc && s <= t) ? expf(sc[k][c] - mval) : 0.0f;
            sc[k][c] = p;
            sum += p;
        }
        #pragma unroll
        for (int o = 16; o; o >>= 1) sum += __shfl_xor_sync(0xffffffffu, sum, o);
        float inv = 1.0f / sum;
        float* arow = attnOut + (size_t)(part*160 + t)*160;
        #pragma unroll
        for (int c = 0; c < 5; ++c) {
            if (c < nc) {
                sc[k][c] *= inv;
                arow[c*32 + lane] = sc[k][c];
            } else {
                arow[c*32 + lane] = 0.0f;
            }
        }
    }

    __syncthreads();

    #pragma unroll
    for (int k = 0; k < 5; ++k) {
        #pragma unroll
        for (int c = 0; c < 5; ++c)
            if (c < nc) sA[(mbase+k)*160 + c*32 + lane] = sc[k][c];
    }
    __syncwarp();

    const float2* sV2 = (const float2*)sV;
    float2 acc[5];
    #pragma unroll
    for (int k = 0; k < 5; ++k) acc[k] = make_float2(0.f, 0.f);

    const int send = (tmax + 4) & ~3;
    for (int s = 0; s < send; s += 4) {
        float4 a[5];
        #pragma unroll
        for (int k = 0; k < 5; ++k)
            a[k] = *(const float4*)(sA + (mbase+k)*160 + s);
        float2 v0 = sV2[(s+0)*32 + lane];
        float2 v1 = sV2[(s+1)*32 + lane];
        float2 v2 = sV2[(s+2)*32 + lane];
        float2 v3 = sV2[(s+3)*32 + lane];
        #pragma unroll
        for (int k = 0; k < 5; ++k) {
            acc[k].x += a[k].x*v0.x + a[k].y*v1.x + a[k].z*v2.x + a[k].w*v3.x;
            acc[k].y += a[k].x*v0.y + a[k].y*v1.y + a[k].z*v2.y + a[k].w*v3.y;
        }
    }
    #pragma unroll
    for (int k = 0; k < 5; ++k) {
        const int t = quad + 4*(mbase + k);
        size_t n = (size_t)part*160 + t;
        ((float2*)(g_z + n*64))[lane] = acc[k];
    }
}

/* ------------------------------------------------------------------ */
/* K3: merged persistent epilogue, 2 blocks/SM (~109.4 KB smem).      */
/* W1 in smem (LDS-heaviest stage); Wo/W2 streamed from L2 as         */
/* coalesced float4 LDGs. Wo and FFN2 fused with their LN stages      */
/* (no partial buffers). 3 barriers/tile. Dynamic tile queue.         */
/* ------------------------------------------------------------------ */
__global__ void __launch_bounds__(512, 2) k_epi(
    const float* __restrict__ Wo, const float* __restrict__ bo,
    const float* __restrict__ ln1g, const float* __restrict__ ln1b,
    const float* __restrict__ W1, const float* __restrict__ b1,
    const float* __restrict__ W2, const float* __restrict__ b2,
    const float* __restrict__ ln2g, const float* __restrict__ ln2b,
    const float* __restrict__ Wf, const float* __restrict__ bf,
    float* __restrict__ outR, float* __restrict__ outP, float* __restrict__ outP2)
{
    extern __shared__ float sm[];
    float* sW1 = sm;            /* 16384 */
    float* sC  = sW1 + 16384;   /* 704: bo|b1|l1g|l1b|b2|l2g|l2b|Wf */
    float* sO1 = sC  + 704;     /* 32 x 64 = 2048 */
    float* sH  = sO1 + 2048;    /* 32 x 256 = 8192 */
    int*   sT  = (int*)(sH + 8192);

    const int tid = threadIdx.x;
    for (int i = tid; i < 4096; i += 512) ((float4*)sW1)[i] = ((const float4*)W1)[i];
    if (tid < 64) {
        sC[tid]     = bo[tid];
        sC[320+tid] = ln1g[tid];
        sC[384+tid] = ln1b[tid];
        sC[448+tid] = b2[tid];
        sC[512+tid] = ln2g[tid];
        sC[576+tid] = ln2b[tid];
        sC[640+tid] = Wf[tid];
    }
    if (tid < 256) sC[64 + tid] = b1[tid];
    const float bfv = bf[0];

    const int rw  = tid >> 4;      /* 0..31 row (Wo / FFN2 stages) */
    const int c4  = tid & 15;      /* float4-col 0..15 */
    const int cqf = tid & 63;      /* FFN1 col-quad */
    const int rqf = tid >> 6;      /* 0..7 -> rows 4rqf.. */

    for (;;) {
        if (tid == 0) sT[0] = atomicAdd(&g_ctrA, 1);
        __syncthreads();
        const int tile = sT[0];
        if (tile >= NTILE) break;
        const int row0 = tile * 32;

        /* ---- S1: Wo (full K=64, 1 row x 4 cols) + bias + resid + LN1 ---- */
        {
            const float* zrow = g_z + (size_t)(row0 + rw)*64;
            float4 accA = {0,0,0,0}, accB = {0,0,0,0};
            #pragma unroll 8
            for (int i = 0; i < 64; i += 2) {
                float a0 = __ldg(zrow + i);
                float a1 = __ldg(zrow + i + 1);
                float4 w0 = __ldg(&((const float4*)(Wo + (i+0)*64))[c4]);
                float4 w1 = __ldg(&((const float4*)(Wo + (i+1)*64))[c4]);
                fma4(accA, a0, w0);
                fma4(accB, a1, w1);
            }
            float4 v;
            float4 b  = ((const float4*)sC)[c4];
            float4 rx = ((const float4*)(g_x + (size_t)(row0 + rw)*64))[c4];
            v.x = accA.x + accB.x + b.x + rx.x;
            v.y = accA.y + accB.y + b.y + rx.y;
            v.z = accA.z + accB.z + b.z + rx.z;
            v.w = accA.w + accB.w + b.w + rx.w;
            float s = v.x + v.y + v.z + v.w;
            #pragma unroll
            for (int o = 8; o; o >>= 1) s += __shfl_xor_sync(0xffffffffu, s, o);
            float mu = s * (1.0f/64.0f);
            float4 d = {v.x-mu, v.y-mu, v.z-mu, v.w-mu};
            float q = d.x*d.x + d.y*d.y + d.z*d.z + d.w*d.w;
            #pragma unroll
            for (int o = 8; o; o >>= 1) q += __shfl_xor_sync(0xffffffffu, q, o);
            float is = rsqrtf(q * (1.0f/64.0f) + 1e-6f);
            float4 g  = ((const float4*)(sC + 320))[c4];
            float4 bb = ((const float4*)(sC + 384))[c4];
            ((float4*)(sO1 + rw*64))[c4] =
                make_float4(g.x*d.x*is + bb.x, g.y*d.y*is + bb.y,
                            g.z*d.z*is + bb.z, g.w*d.w*is + bb.w);
        }
        __syncthreads();

        /* ---- S2: FFN1 4x4 (W1 in smem) + relu -> sH ---- */
        {
            float4 b = ((const float4*)(sC + 64))[cqf];
            float4 acc0 = b, acc1 = b, acc2 = b, acc3 = b;
            #pragma unroll 4
            for (int i4 = 0; i4 < 16; ++i4) {
                float4 w0 = ((const float4*)(sW1 + (i4*4+0)*256))[cqf];
                float4 w1 = ((const float4*)(sW1 + (i4*4+1)*256))[cqf];
                float4 w2 = ((const float4*)(sW1 + (i4*4+2)*256))[cqf];
                float4 w3 = ((const float4*)(sW1 + (i4*4+3)*256))[cqf];
                float4 a0 = ((const float4*)(sO1 + (4*rqf+0)*64))[i4];
                float4 a1 = ((const float4*)(sO1 + (4*rqf+1)*64))[i4];
                float4 a2 = ((const float4*)(sO1 + (4*rqf+2)*64))[i4];
                float4 a3 = ((const float4*)(sO1 + (4*rqf+3)*64))[i4];
                fma4(acc0, a0.x, w0); fma4(acc0, a0.y, w1); fma4(acc0, a0.z, w2); fma4(acc0, a0.w, w3);
                fma4(acc1, a1.x, w0); fma4(acc1, a1.y, w1); fma4(acc1, a1.z, w2); fma4(acc1, a1.w, w3);
                fma4(acc2, a2.x, w0); fma4(acc2, a2.y, w1); fma4(acc2, a2.z, w2); fma4(acc2, a2.w, w3);
                fma4(acc3, a3.x, w0); fma4(acc3, a3.y, w1); fma4(acc3, a3.z, w2); fma4(acc3, a3.w, w3);
            }
            acc0.x = fmaxf(acc0.x, 0.f); acc0.y = fmaxf(acc0.y, 0.f);
            acc0.z = fmaxf(acc0.z, 0.f); acc0.w = fmaxf(acc0.w, 0.f);
            acc1.x = fmaxf(acc1.x, 0.f); acc1.y = fmaxf(acc1.y, 0.f);
            acc1.z = fmaxf(acc1.z, 0.f); acc1.w = fmaxf(acc1.w, 0.f);
            acc2.x = fmaxf(acc2.x, 0.f); acc2.y = fmaxf(acc2.y, 0.f);
            acc2.z = fmaxf(acc2.z, 0.f); acc2.w = fmaxf(acc2.w, 0.f);
            acc3.x = fmaxf(acc3.x, 0.f); acc3.y = fmaxf(acc3.y, 0.f);
            acc3.z = fmaxf(acc3.z, 0.f); acc3.w = fmaxf(acc3.w, 0.f);
            ((float4*)(sH + (4*rqf+0)*256))[cqf] = acc0;
            ((float4*)(sH + (4*rqf+1)*256))[cqf] = acc1;
            ((float4*)(sH + (4*rqf+2)*256))[cqf] = acc2;
            ((float4*)(sH + (4*rqf+3)*256))[cqf] = acc3;
        }
        __syncthreads();

        /* ---- S3: FFN2 (full K=256, W2 streamed) + resid + LN2 + out ---- */
        {
            const float* hrow = sH + rw*256;
            float4 accA = {0,0,0,0}, accB = {0,0,0,0};
            #pragma unroll 8
            for (int i = 0; i < 256; i += 2) {
                float a0 = hrow[i];
                float a1 = hrow[i + 1];
                float4 w0 = __ldg(&((const float4*)(W2 + (i+0)*64))[c4]);
                float4 w1 = __ldg(&((const float4*)(W2 + (i+1)*64))[c4]);
                fma4(accA, a0, w0);
                fma4(accB, a1, w1);
            }
            float4 v;
            float4 b  = ((const float4*)(sC + 448))[c4];
            float4 rs = ((const float4*)(sO1 + rw*64))[c4];
            v.x = accA.x + accB.x + b.x + rs.x;
            v.y = accA.y + accB.y + b.y + rs.y;
            v.z = accA.z + accB.z + b.z + rs.z;
            v.w = accA.w + accB.w + b.w + rs.w;
            float s = v.x + v.y + v.z + v.w;
            #pragma unroll
            for (int o = 8; o; o >>= 1) s += __shfl_xor_sync(0xffffffffu, s, o);
            float mu = s * (1.0f/64.0f);
            float4 d = {v.x-mu, v.y-mu, v.z-mu, v.w-mu};
            float q = d.x*d.x + d.y*d.y + d.z*d.z + d.w*d.w;
            #pragma unroll
            for (int o = 8; o; o >>= 1) q += __shfl_xor_sync(0xffffffffu, q, o);
            float is = rsqrtf(q * (1.0f/64.0f) + 1e-6f);
            float4 g  = ((const float4*)(sC + 512))[c4];
            float4 bb = ((const float4*)(sC + 576))[c4];
            float4 rv = {g.x*d.x*is + bb.x, g.y*d.y*is + bb.y,
                         g.z*d.z*is + bb.z, g.w*d.w*is + bb.w};
            const size_t n = (size_t)row0 + rw;
            ((float4*)(outR + n*64))[c4] = rv;
            float4 wf = ((const float4*)(sC + 640))[c4];
            float pp = rv.x*wf.x + rv.y*wf.y + rv.z*wf.z + rv.w*wf.w;
            #pragma unroll
            for (int o = 8; o; o >>= 1) pp += __shfl_xor_sync(0xffffffffu, pp, o);
            if (c4 == 0) {
                float pv = pp + bfv;
                outP[n]  = pv;
                outP2[n] = pv;
            }
        }
        __syncthreads();
    }
}

/* ------------------------------------------------------------------ */
extern "C" void kernel_launch(void* const* d_in, const int* in_sizes, int n_in,
                              void* d_out, int out_size)
{
    (void)in_sizes; (void)n_in; (void)out_size;
    const float* inputs = (const float*)d_in[0];
    const float* Wp  = (const float*)d_in[2];
    const float* bp  = (const float*)d_in[3];
    const float* Wq  = (const float*)d_in[4];
    const float* bq  = (const float*)d_in[5];
    const float* Wk  = (const float*)d_in[6];
    const float* bk  = (const float*)d_in[7];
    const float* Wv  = (const float*)d_in[8];
    const float* bv  = (const float*)d_in[9];
    const float* Wo  = (const float*)d_in[10];
    const float* bo  = (const float*)d_in[11];
    const float* l1g = (const float*)d_in[12];
    const float* l1b = (const float*)d_in[13];
    const float* W1  = (const float*)d_in[14];
    const float* b1  = (const float*)d_in[15];
    const float* W2  = (const float*)d_in[16];
    const float* b2  = (const float*)d_in[17];
    const float* l2g = (const float*)d_in[18];
    const float* l2b = (const float*)d_in[19];
    const float* Wf  = (const float*)d_in[20];
    const float* bf  = (const float*)d_in[21];
    float* out = (float*)d_out;

    const size_t sm1 = (size_t)(2816 + 256 + 704) * 4;                    /* ~15 KB  */
    const size_t sm2 = (size_t)(10304 + 10240 + 2560) * 4;                /* ~92 KB  */
    const size_t sm3 = (size_t)(16384 + 704 + 2048 + 8192 + 4) * 4;       /* ~109.4 KB */

    cudaFuncSetAttribute(k_qkv,  cudaFuncAttributeMaxDynamicSharedMemorySize, (int)sm1);
    cudaFuncSetAttribute(k_attn, cudaFuncAttributeMaxDynamicSharedMemorySize, (int)sm2);
    cudaFuncSetAttribute(k_epi,  cudaFuncAttributeMaxDynamicSharedMemorySize, (int)sm3);

    k_fold<<<4, 256>>>(Wp, bp, Wq, bq, Wk, bk, Wv, bv);
    k_qkv<<<NROW/64, 512, sm1>>>(inputs, out + OFF_K, out + OFF_V);
    k_attn<<<NPART*4, 256, sm2>>>(out + OFF_K, out + OFF_V, out + OFF_ATTN);
    k_epi<<<296, 512, sm3>>>(Wo, bo, l1g, l1b, W1, b1, W2, b2, l2g, l2b, Wf, bf,
                             out + OFF_R, out + OFF_PRED, out + OFF_PRED2);
}

// round 12
// speedup vs baseline: 1.2195x; 1.1121x over previous
#include <cuda_runtime.h>

#define B_ 8
#define P_ 10
#define S_ 160
#define FX_ 11
#define D_ 64
#define DFF_ 256
#define NROW (B_*P_*S_)   /* 12800 */
#define NPART (B_*P_)     /* 80 */
#define NQKV  (NROW/64)   /* 200 qkv blocks */

/* output layout (tuple order): pred, pred_resampl, K, V, R, attn_weights */
#define OFF_PRED  0
#define OFF_PRED2 (NROW)
#define OFF_K     (2*NROW)
#define OFF_V     (OFF_K + NROW*D_)
#define OFF_R     (OFF_V + NROW*D_)
#define OFF_ATTN  (OFF_R + NROW*D_)

/* scratch (no cudaMalloc allowed) */
__device__ float g_x[NROW*D_];
__device__ float g_q[NROW*D_];
__device__ float g_z[NROW*D_];
__device__ float g_fw[4*704];   /* fused 11x64 weights: x,q,k,v */
__device__ float g_fb[4*64];    /* fused biases */
__device__ int   g_cntQ;        /* qkv completion counter */

__device__ __forceinline__ void fma4(float4& acc, float s, const float4& v) {
    acc.x += s * v.x; acc.y += s * v.y; acc.z += s * v.z; acc.w += s * v.w;
}

/* ------------------------------------------------------------------ */
/* K0: fold Wp into Wq/Wk/Wv. Attention scale 1/8 folded into Wq.     */
/* Also resets the qkv completion counter (graph-replay safe).        */
/* ------------------------------------------------------------------ */
__global__ void __launch_bounds__(256) k_fold(
    const float* __restrict__ Wp, const float* __restrict__ bp,
    const float* __restrict__ Wq, const float* __restrict__ bq,
    const float* __restrict__ Wk, const float* __restrict__ bk,
    const float* __restrict__ Wv, const float* __restrict__ bv)
{
    __shared__ float sWp[704];
    __shared__ float sW[4096];
    const int b = blockIdx.x, tid = threadIdx.x;
    if (b == 0) {
        if (tid == 0) g_cntQ = 0;
        for (int i = tid; i < 704; i += 256) g_fw[i] = 8.0f * Wp[i];
        if (tid < 64) g_fb[tid] = 8.0f * bp[tid];
        return;
    }
    const float* W  = (b == 1) ? Wq : (b == 2) ? Wk : Wv;
    const float* bb = (b == 1) ? bq : (b == 2) ? bk : bv;
    const float fw = (b == 1) ? 1.0f   : 8.0f;   /* 8 * (1/8 attn scale) for q */
    const float fb = (b == 1) ? 0.125f : 1.0f;
    for (int i = tid; i < 704;  i += 256) sWp[i] = Wp[i];
    for (int i = tid; i < 4096; i += 256) sW[i]  = W[i];
    __syncthreads();
    const int j = tid & 63, g = tid >> 6;
    for (int i = g; i < 11; i += 4) {
        float s = 0.0f;
        #pragma unroll 4
        for (int d = 0; d < 64; ++d) s += sWp[i*64 + d] * sW[d*64 + j];
        g_fw[b*704 + i*64 + j] = fw * s;
    }
    if (tid < 64) {
        float s = 0.0f;
        for (int d = 0; d < 64; ++d) s += bp[d] * sW[d*64 + tid];
        g_fb[b*64 + tid] = fw * s + fb * bb[tid];
    }
}

/* ------------------------------------------------------------------ */
/* score helper for attn phase                                        */
/* ------------------------------------------------------------------ */
template<int NC>
__device__ __forceinline__ void score_nc(
    const float* __restrict__ sKt, const float* __restrict__ sQ,
    int mbase, int lane, float (&sc)[5][5])
{
    #pragma unroll 2
    for (int i = 0; i < 64; ++i) {
        float kv[NC];
        #pragma unroll
        for (int c = 0; c < NC; ++c) kv[c] = sKt[i*161 + c*32 + lane];
        #pragma unroll
        for (int k = 0; k < 5; ++k) {
            float qi = sQ[(mbase+k)*64 + i];
            #pragma unroll
            for (int c = 0; c < NC; ++c) sc[k][c] += qi * kv[c];
        }
    }
}

/* ------------------------------------------------------------------ */
/* K1: fused qkv + attention.                                         */
/* blocks [0,200): qkv (64 rows each), signal g_cntQ when done.       */
/* blocks [200,520): attention; spin until g_cntQ == 200.             */
/* ------------------------------------------------------------------ */
__global__ void __launch_bounds__(512) k_fused(
    const float* __restrict__ inp,
    float* __restrict__ Kio, float* __restrict__ Vio,
    float* __restrict__ attnOut)
{
    extern __shared__ float sm[];
    const int tid = threadIdx.x;

    if (blockIdx.x < NQKV) {
        /* ======================= qkv phase ======================= */
        float* sW  = sm;          /* 2816 */
        float* sB  = sW + 2816;   /* 256  */
        float* sIn = sB + 256;    /* 704  */
        const int row0 = blockIdx.x * 64;

        for (int i = tid; i < 2816; i += 512) sW[i] = g_fw[i];
        if (tid < 256) sB[tid] = g_fb[tid];
        for (int i = tid; i < 704; i += 512) sIn[i] = inp[(size_t)row0*11 + i];
        __syncthreads();

        const int j = tid & 63, rb = (tid >> 6) * 8;
        float wx[11], wq[11], wk[11], wv[11];
        #pragma unroll
        for (int i = 0; i < 11; ++i) {
            wx[i] = sW[i*64 + j];
            wq[i] = sW[704  + i*64 + j];
            wk[i] = sW[1408 + i*64 + j];
            wv[i] = sW[2112 + i*64 + j];
        }
        float ax[8], aq[8], ak[8], av[8];
        #pragma unroll
        for (int r = 0; r < 8; ++r) {
            ax[r] = sB[j]; aq[r] = sB[64+j]; ak[r] = sB[128+j]; av[r] = sB[192+j];
        }
        #pragma unroll
        for (int i = 0; i < 11; ++i) {
            #pragma unroll
            for (int r = 0; r < 8; ++r) {
                float in = sIn[(rb+r)*11 + i];
                ax[r] += in * wx[i];
                aq[r] += in * wq[i];
                ak[r] += in * wk[i];
                av[r] += in * wv[i];
            }
        }
        #pragma unroll
        for (int r = 0; r < 8; ++r) {
            size_t n = (size_t)(row0 + rb + r) * 64 + j;
            g_x[n]   = ax[r];
            g_q[n]   = aq[r];
            Kio[n]   = ak[r];
            Vio[n]   = av[r];
        }
        /* signal completion (canonical threadFence pattern) */
        __syncthreads();
        if (tid == 0) {
            __threadfence();
            atomicAdd(&g_cntQ, 1);
        }
        return;
    }

    /* ======================== attn phase ======================== */
    /* wait for all qkv producers */
    if (tid == 0) {
        while (atomicAdd(&g_cntQ, 0) < NQKV) __nanosleep(64);
    }
    __syncthreads();
    __threadfence();

    float* sKt = sm;             /* 64 x 161 = 10304; reused as sA */
    float* sV  = sKt + 10304;    /* 160 x 64 = 10240 */
    float* sQ  = sV  + 10240;    /* 40 x 64  = 2560  */
    float* sA  = sKt;

    const int bid  = blockIdx.x - NQKV;
    const int lane = tid & 31;
    const int w    = tid >> 5;          /* 0..15; warps 8..15 idle in compute */
    const int part = bid >> 2;
    const int quad = bid & 3;

    const float4* Kg4 = (const float4*)(Kio + (size_t)part*160*64);
    const float4* Vg4 = (const float4*)(Vio + (size_t)part*160*64);
    float4* sV4 = (float4*)sV;

    for (int idx = tid; idx < 160*16; idx += 512) {
        int s = idx >> 4, i4 = (idx & 15) * 4;
        float4 kk = Kg4[idx];
        sKt[(i4+0)*161 + s] = kk.x;
        sKt[(i4+1)*161 + s] = kk.y;
        sKt[(i4+2)*161 + s] = kk.z;
        sKt[(i4+3)*161 + s] = kk.w;
        sV4[idx] = Vg4[idx];
    }
    for (int idx = tid; idx < 40*16; idx += 512) {
        int m = idx >> 4, i4 = idx & 15;
        int row = part*160 + quad + 4*m;
        ((float4*)(sQ + m*64))[i4] = ((const float4*)(g_q + (size_t)row*64))[i4];
    }
    __syncthreads();

    if (w < 8) {
        const int r     = (w < 4) ? w : 11 - w;
        const int mbase = 5 * r;
        const int tmax  = quad + 20*r + 16;
        const int nc    = (tmax >> 5) + 1;

        float sc[5][5];
        #pragma unroll
        for (int k = 0; k < 5; ++k)
            #pragma unroll
            for (int c = 0; c < 5; ++c) sc[k][c] = 0.0f;

        switch (nc) {
            case 1: score_nc<1>(sKt, sQ, mbase, lane, sc); break;
            case 2: score_nc<2>(sKt, sQ, mbase, lane, sc); break;
            case 3: score_nc<3>(sKt, sQ, mbase, lane, sc); break;
            case 4: score_nc<4>(sKt, sQ, mbase, lane, sc); break;
            default: score_nc<5>(sKt, sQ, mbase, lane, sc); break;
        }

        #pragma unroll
        for (int k = 0; k < 5; ++k) {
            const int t = quad + 4*(mbase + k);
            float mval = -3.4e38f;
            #pragma unroll
            for (int c = 0; c < 5; ++c) {
                int s = c*32 + lane;
                if (c < nc && s <= t) mval = fmaxf(mval, sc[k][c]);
            }
            #pragma unroll
            for (int o = 16; o; o >>= 1) mval = fmaxf(mval, __shfl_xor_sync(0xffffffffu, mval, o));
            float sum = 0.0f;
            #pragma unroll
            for (int c = 0; c < 5; ++c) {
                int s = c*32 + lane;
                float p = (c < nc && s <= t) ? expf(sc[k][c] - mval) : 0.0f;
                sc[k][c] = p;
                sum += p;
            }
            #pragma unroll
            for (int o = 16; o; o >>= 1) sum += __shfl_xor_sync(0xffffffffu, sum, o);
            float inv = 1.0f / sum;
            float* arow = attnOut + (size_t)(part*160 + t)*160;
            #pragma unroll
            for (int c = 0; c < 5; ++c) {
                if (c < nc) {
                    sc[k][c] *= inv;
                    arow[c*32 + lane] = sc[k][c];
                } else {
                    arow[c*32 + lane] = 0.0f;
                }
            }
        }

        __syncthreads();   /* pairs with barrier below (all warps) */

        #pragma unroll
        for (int k = 0; k < 5; ++k) {
            #pragma unroll
            for (int c = 0; c < 5; ++c)
                if (c < nc) sA[(mbase+k)*160 + c*32 + lane] = sc[k][c];
        }
        __syncwarp();

        const float2* sV2 = (const float2*)sV;
        float2 acc[5];
        #pragma unroll
        for (int k = 0; k < 5; ++k) acc[k] = make_float2(0.f, 0.f);

        const int send = (tmax + 4) & ~3;
        for (int s = 0; s < send; s += 4) {
            float4 a[5];
            #pragma unroll
            for (int k = 0; k < 5; ++k)
                a[k] = *(const float4*)(sA + (mbase+k)*160 + s);
            float2 v0 = sV2[(s+0)*32 + lane];
            float2 v1 = sV2[(s+1)*32 + lane];
            float2 v2 = sV2[(s+2)*32 + lane];
            float2 v3 = sV2[(s+3)*32 + lane];
            #pragma unroll
            for (int k = 0; k < 5; ++k) {
                acc[k].x += a[k].x*v0.x + a[k].y*v1.x + a[k].z*v2.x + a[k].w*v3.x;
                acc[k].y += a[k].x*v0.y + a[k].y*v1.y + a[k].z*v2.y + a[k].w*v3.y;
            }
        }
        #pragma unroll
        for (int k = 0; k < 5; ++k) {
            const int t = quad + 4*(mbase + k);
            size_t n = (size_t)part*160 + t;
            ((float2*)(g_z + n*64))[lane] = acc[k];
        }
    } else {
        __syncthreads();   /* idle warps participate in the mid barrier */
    }
}

/* ------------------------------------------------------------------ */
/* K3: persistent epilogue (R5 best-measured version, verbatim).      */
/* ------------------------------------------------------------------ */
__global__ void __launch_bounds__(512) k_epi(
    const float* __restrict__ Wo, const float* __restrict__ bo,
    const float* __restrict__ ln1g, const float* __restrict__ ln1b,
    const float* __restrict__ W1, const float* __restrict__ b1,
    const float* __restrict__ W2, const float* __restrict__ b2,
    const float* __restrict__ ln2g, const float* __restrict__ ln2b,
    const float* __restrict__ Wf, const float* __restrict__ bf,
    float* __restrict__ outR, float* __restrict__ outP, float* __restrict__ outP2)
{
    extern __shared__ float sm[];
    float* sWo = sm;            /* 4096  */
    float* sW1 = sWo + 4096;    /* 16384 */
    float* sW2 = sW1 + 16384;   /* 16384 */
    float* sC  = sW2 + 16384;   /* 704 */
    float* sO1 = sC  + 704;     /* 2048 */
    float* sH  = sO1 + 2048;    /* 8192 (also Wo partials 4x2048) */
    float* sP  = sH  + 8192;    /* 4096: FFN2 partials 2x2048 */

    const int tid = threadIdx.x, lane = tid & 31, w = tid >> 5;

    for (int i = tid; i < 1024; i += 512) ((float4*)sWo)[i] = ((const float4*)Wo)[i];
    for (int i = tid; i < 4096; i += 512) {
        ((float4*)sW1)[i] = ((const float4*)W1)[i];
        ((float4*)sW2)[i] = ((const float4*)W2)[i];
    }
    if (tid < 64) {
        sC[tid]     = bo[tid];
        sC[320+tid] = b2[tid];
        sC[384+tid] = ln1g[tid];
        sC[448+tid] = ln1b[tid];
        sC[512+tid] = ln2g[tid];
        sC[576+tid] = ln2b[tid];
        sC[640+tid] = Wf[tid];
    }
    if (tid < 256) sC[64 + tid] = b1[tid];
    const float bfv = bf[0];
    __syncthreads();

    for (int tile = blockIdx.x; tile < NROW/32; tile += gridDim.x) {
        const int row0 = tile * 32;

        /* (1) Wo: 4-way K-split, 4 rows x 4 cols */
        {
            const int isp = tid >> 7;
            const int t1  = tid & 127;
            const int cq  = t1 & 15;
            const int rq  = t1 >> 4;
            float4 acc0 = {0,0,0,0}, acc1 = {0,0,0,0}, acc2 = {0,0,0,0}, acc3 = {0,0,0,0};
            #pragma unroll
            for (int i4 = isp*4; i4 < isp*4 + 4; ++i4) {
                float4 w0 = ((const float4*)(sWo + (i4*4+0)*64))[cq];
                float4 w1 = ((const float4*)(sWo + (i4*4+1)*64))[cq];
                float4 w2 = ((const float4*)(sWo + (i4*4+2)*64))[cq];
                float4 w3 = ((const float4*)(sWo + (i4*4+3)*64))[cq];
                float4 a0 = ((const float4*)(g_z + (size_t)(row0 + 4*rq+0)*64))[i4];
                float4 a1 = ((const float4*)(g_z + (size_t)(row0 + 4*rq+1)*64))[i4];
                float4 a2 = ((const float4*)(g_z + (size_t)(row0 + 4*rq+2)*64))[i4];
                float4 a3 = ((const float4*)(g_z + (size_t)(row0 + 4*rq+3)*64))[i4];
                fma4(acc0, a0.x, w0); fma4(acc0, a0.y, w1); fma4(acc0, a0.z, w2); fma4(acc0, a0.w, w3);
                fma4(acc1, a1.x, w0); fma4(acc1, a1.y, w1); fma4(acc1, a1.z, w2); fma4(acc1, a1.w, w3);
                fma4(acc2, a2.x, w0); fma4(acc2, a2.y, w1); fma4(acc2, a2.z, w2); fma4(acc2, a2.w, w3);
                fma4(acc3, a3.x, w0); fma4(acc3, a3.y, w1); fma4(acc3, a3.z, w2); fma4(acc3, a3.w, w3);
            }
            float4* dst = (float4*)(sH + isp*2048);
            dst[(4*rq+0)*16 + cq] = acc0;
            dst[(4*rq+1)*16 + cq] = acc1;
            dst[(4*rq+2)*16 + cq] = acc2;
            dst[(4*rq+3)*16 + cq] = acc3;
        }
        __syncthreads();
        /* (2) reduce + bias + residual + LN1 -> sO1 */
        {
            const float4* p = (const float4*)sH;
            float4 v = p[tid];
            float4 v1 = p[512 + tid], v2 = p[1024 + tid], v3 = p[1536 + tid];
            const int row = tid >> 4, c4 = tid & 15;
            float4 b = ((const float4*)sC)[c4];
            float4 rx = ((const float4*)(g_x + (size_t)(row0 + row)*64))[c4];
            v.x += v1.x + v2.x + v3.x + b.x + rx.x;
            v.y += v1.y + v2.y + v3.y + b.y + rx.y;
            v.z += v1.z + v2.z + v3.z + b.z + rx.z;
            v.w += v1.w + v2.w + v3.w + b.w + rx.w;
            float s = v.x + v.y + v.z + v.w;
            #pragma unroll
            for (int o = 8; o; o >>= 1) s += __shfl_xor_sync(0xffffffffu, s, o);
            float mu = s * (1.0f/64.0f);
            float4 d = {v.x-mu, v.y-mu, v.z-mu, v.w-mu};
            float q = d.x*d.x + d.y*d.y + d.z*d.z + d.w*d.w;
            #pragma unroll
            for (int o = 8; o; o >>= 1) q += __shfl_xor_sync(0xffffffffu, q, o);
            float is = rsqrtf(q * (1.0f/64.0f) + 1e-6f);
            float4 g = ((const float4*)(sC + 384))[c4];
            float4 bb = ((const float4*)(sC + 448))[c4];
            float4 o1 = {g.x*d.x*is + bb.x, g.y*d.y*is + bb.y,
                         g.z*d.z*is + bb.z, g.w*d.w*is + bb.w};
            ((float4*)sO1)[tid] = o1;
        }
        __syncthreads();

        /* (3) FFN1 4x4 + relu */
        {
            const int cq = tid & 63;
            const int rq = tid >> 6;
            float4 b = ((const float4*)(sC + 64))[cq];
            float4 acc0 = b, acc1 = b, acc2 = b, acc3 = b;
            #pragma unroll 4
            for (int i4 = 0; i4 < 16; ++i4) {
                float4 w0 = ((const float4*)(sW1 + (i4*4+0)*256))[cq];
                float4 w1 = ((const float4*)(sW1 + (i4*4+1)*256))[cq];
                float4 w2 = ((const float4*)(sW1 + (i4*4+2)*256))[cq];
                float4 w3 = ((const float4*)(sW1 + (i4*4+3)*256))[cq];
                float4 a0 = ((const float4*)(sO1 + (4*rq+0)*64))[i4];
                float4 a1 = ((const float4*)(sO1 + (4*rq+1)*64))[i4];
                float4 a2 = ((const float4*)(sO1 + (4*rq+2)*64))[i4];
                float4 a3 = ((const float4*)(sO1 + (4*rq+3)*64))[i4];
                fma4(acc0, a0.x, w0); fma4(acc0, a0.y, w1); fma4(acc0, a0.z, w2); fma4(acc0, a0.w, w3);
                fma4(acc1, a1.x, w0); fma4(acc1, a1.y, w1); fma4(acc1, a1.z, w2); fma4(acc1, a1.w, w3);
                fma4(acc2, a2.x, w0); fma4(acc2, a2.y, w1); fma4(acc2, a2.z, w2); fma4(acc2, a2.w, w3);
                fma4(acc3, a3.x, w0); fma4(acc3, a3.y, w1); fma4(acc3, a3.z, w2); fma4(acc3, a3.w, w3);
            }
            acc0.x = fmaxf(acc0.x, 0.f); acc0.y = fmaxf(acc0.y, 0.f);
            acc0.z = fmaxf(acc0.z, 0.f); acc0.w = fmaxf(acc0.w, 0.f);
            acc1.x = fmaxf(acc1.x, 0.f); acc1.y = fmaxf(acc1.y, 0.f);
            acc1.z = fmaxf(acc1.z, 0.f); acc1.w = fmaxf(acc1.w, 0.f);
            acc2.x = fmaxf(acc2.x, 0.f); acc2.y = fmaxf(acc2.y, 0.f);
            acc2.z = fmaxf(acc2.z, 0.f); acc2.w = fmaxf(acc2.w, 0.f);
            acc3.x = fmaxf(acc3.x, 0.f); acc3.y = fmaxf(acc3.y, 0.f);
            acc3.z = fmaxf(acc3.z, 0.f); acc3.w = fmaxf(acc3.w, 0.f);
            ((float4*)(sH + (4*rq+0)*256))[cq] = acc0;
            ((float4*)(sH + (4*rq+1)*256))[cq] = acc1;
            ((float4*)(sH + (4*rq+2)*256))[cq] = acc2;
            ((float4*)(sH + (4*rq+3)*256))[cq] = acc3;
        }
        __syncthreads();

        /* (4) FFN2: 2-way K-split, 2 rows x 4 cols */
        {
            const int isp = tid >> 8;
            const int t2  = tid & 255;
            const int cq  = t2 & 15;
            const int rq  = t2 >> 4;
            float4 acc0 = {0,0,0,0}, acc1 = {0,0,0,0};
            #pragma unroll 4
            for (int i4 = isp*32; i4 < isp*32 + 32; ++i4) {
                float4 w0 = ((const float4*)(sW2 + (i4*4+0)*64))[cq];
                float4 w1 = ((const float4*)(sW2 + (i4*4+1)*64))[cq];
                float4 w2 = ((const float4*)(sW2 + (i4*4+2)*64))[cq];
                float4 w3 = ((const float4*)(sW2 + (i4*4+3)*64))[cq];
                float4 a0 = ((const float4*)(sH + (2*rq+0)*256))[i4];
                float4 a1 = ((const float4*)(sH + (2*rq+1)*256))[i4];
                fma4(acc0, a0.x, w0); fma4(acc0, a0.y, w1); fma4(acc0, a0.z, w2); fma4(acc0, a0.w, w3);
                fma4(acc1, a1.x, w0); fma4(acc1, a1.y, w1); fma4(acc1, a1.z, w2); fma4(acc1, a1.w, w3);
            }
            float4* dst = (float4*)(sP + isp*2048);
            dst[(2*rq+0)*16 + cq] = acc0;
            dst[(2*rq+1)*16 + cq] = acc1;
        }
        __syncthreads();
        /* (5) reduce + bias + residual + LN2 + outputs */
        {
            const float4* p = (const float4*)sP;
            float4 v = p[tid];
            float4 v1 = p[512 + tid];
            const int row = tid >> 4, c4 = tid & 15;
            float4 b = ((const float4*)(sC + 320))[c4];
            float4 rs = ((const float4*)sO1)[tid];
            v.x += v1.x + b.x + rs.x;
            v.y += v1.y + b.y + rs.y;
            v.z += v1.z + b.z + rs.z;
            v.w += v1.w + b.w + rs.w;
            float s = v.x + v.y + v.z + v.w;
            #pragma unroll
            for (int o = 8; o; o >>= 1) s += __shfl_xor_sync(0xffffffffu, s, o);
            float mu = s * (1.0f/64.0f);
            float4 d = {v.x-mu, v.y-mu, v.z-mu, v.w-mu};
            float q = d.x*d.x + d.y*d.y + d.z*d.z + d.w*d.w;
            #pragma unroll
            for (int o = 8; o; o >>= 1) q += __shfl_xor_sync(0xffffffffu, q, o);
            float is = rsqrtf(q * (1.0f/64.0f) + 1e-6f);
            float4 g = ((const float4*)(sC + 512))[c4];
            float4 bb = ((const float4*)(sC + 576))[c4];
            float4 rv = {g.x*d.x*is + bb.x, g.y*d.y*is + bb.y,
                         g.z*d.z*is + bb.z, g.w*d.w*is + bb.w};
            const size_t n = (size_t)row0 + row;
            ((float4*)(outR + n*64))[c4] = rv;
            float4 wf = ((const float4*)(sC + 640))[c4];
            float pp = rv.x*wf.x + rv.y*wf.y + rv.z*wf.z + rv.w*wf.w;
            #pragma unroll
            for (int o = 8; o; o >>= 1) pp += __shfl_xor_sync(0xffffffffu, pp, o);
            if (c4 == 0) {
                float pv = pp + bfv;
                outP[n]  = pv;
                outP2[n] = pv;
            }
        }
        __syncthreads();
    }
}

/* ------------------------------------------------------------------ */
extern "C" void kernel_launch(void* const* d_in, const int* in_sizes, int n_in,
                              void* d_out, int out_size)
{
    (void)in_sizes; (void)n_in; (void)out_size;
    const float* inputs = (const float*)d_in[0];
    const float* Wp  = (const float*)d_in[2];
    const float* bp  = (const float*)d_in[3];
    const float* Wq  = (const float*)d_in[4];
    const float* bq  = (const float*)d_in[5];
    const float* Wk  = (const float*)d_in[6];
    const float* bk  = (const float*)d_in[7];
    const float* Wv  = (const float*)d_in[8];
    const float* bv  = (const float*)d_in[9];
    const float* Wo  = (const float*)d_in[10];
    const float* bo  = (const float*)d_in[11];
    const float* l1g = (const float*)d_in[12];
    const float* l1b = (const float*)d_in[13];
    const float* W1  = (const float*)d_in[14];
    const float* b1  = (const float*)d_in[15];
    const float* W2  = (const float*)d_in[16];
    const float* b2  = (const float*)d_in[17];
    const float* l2g = (const float*)d_in[18];
    const float* l2b = (const float*)d_in[19];
    const float* Wf  = (const float*)d_in[20];
    const float* bf  = (const float*)d_in[21];
    float* out = (float*)d_out;

    const size_t smF = (size_t)(10304 + 10240 + 2560) * 4;                      /* ~92 KB */
    const size_t sm3 = (size_t)(4096 + 16384 + 16384 + 704 + 2048 + 8192 + 4096) * 4; /* ~203 KB */

    cudaFuncSetAttribute(k_fused, cudaFuncAttributeMaxDynamicSharedMemorySize, (int)smF);
    cudaFuncSetAttribute(k_epi,   cudaFuncAttributeMaxDynamicSharedMemorySize, (int)sm3);

    k_fold<<<4, 256>>>(Wp, bp, Wq, bq, Wk, bk, Wv, bv);
    k_fused<<<NQKV + NPART*4, 512, smF>>>(inputs, out + OFF_K, out + OFF_V,
                                          out + OFF_ATTN);
    k_epi<<<148, 512, sm3>>>(Wo, bo, l1g, l1b, W1, b1, W2, b2, l2g, l2b, Wf, bf,
                             out + OFF_R, out + OFF_PRED, out + OFF_PRED2);
}

// round 13
// speedup vs baseline: 1.3829x; 1.1340x over previous
#include <cuda_runtime.h>

#define B_ 8
#define P_ 10
#define S_ 160
#define FX_ 11
#define D_ 64
#define DFF_ 256
#define NROW (B_*P_*S_)   /* 12800 */
#define NPART (B_*P_)     /* 80 */

/* output layout (tuple order): pred, pred_resampl, K, V, R, attn_weights */
#define OFF_PRED  0
#define OFF_PRED2 (NROW)
#define OFF_K     (2*NROW)
#define OFF_V     (OFF_K + NROW*D_)
#define OFF_R     (OFF_V + NROW*D_)
#define OFF_ATTN  (OFF_R + NROW*D_)

/* scratch (no cudaMalloc allowed) */
__device__ float g_x[NROW*D_];
__device__ float g_q[NROW*D_];
__device__ float g_z[NROW*D_];
__device__ float g_fw[4*704];   /* fused 11x64 weights: x,q,k,v */
__device__ float g_fb[4*64];    /* fused biases */

__device__ __forceinline__ void fma4(float4& acc, float s, const float4& v) {
    acc.x += s * v.x; acc.y += s * v.y; acc.z += s * v.z; acc.w += s * v.w;
}

/* ------------------------------------------------------------------ */
/* K0: fold Wp into Wq/Wk/Wv. PARALLEL: 35 blocks.                    */
/*   b=0        : x-path copy (8*Wp, 8*bp)                            */
/*   b=1..33    : one (type,row) each, 4-way K-split + smem reduce    */
/*   b=34       : the three fused biases                              */
/* Attention scale 1/8 folded into Wq path.                           */
/* ------------------------------------------------------------------ */
__global__ void __launch_bounds__(256) k_fold(
    const float* __restrict__ Wp, const float* __restrict__ bp,
    const float* __restrict__ Wq, const float* __restrict__ bq,
    const float* __restrict__ Wk, const float* __restrict__ bk,
    const float* __restrict__ Wv, const float* __restrict__ bv)
{
    __shared__ float red[256];
    const int b = blockIdx.x, tid = threadIdx.x;

    if (b == 0) {
        for (int i = tid; i < 704; i += 256) g_fw[i] = 8.0f * Wp[i];
        if (tid < 64) g_fb[tid] = 8.0f * bp[tid];
        return;
    }
    const int j = tid & 63, p = tid >> 6;

    if (b <= 33) {
        const int t = (b - 1) / 11 + 1;     /* 1=q, 2=k, 3=v */
        const int i = (b - 1) % 11;
        const float* W  = (t == 1) ? Wq : (t == 2) ? Wk : Wv;
        const float fw  = (t == 1) ? 1.0f : 8.0f;
        float s = 0.0f;
        #pragma unroll
        for (int d = p*16; d < p*16 + 16; ++d)
            s += Wp[i*64 + d] * W[d*64 + j];
        red[tid] = s;
        __syncthreads();
        if (p == 0)
            g_fw[t*704 + i*64 + j] =
                fw * (red[j] + red[64+j] + red[128+j] + red[192+j]);
        return;
    }

    /* b == 34: fused biases for q,k,v */
    #pragma unroll
    for (int t = 1; t <= 3; ++t) {
        const float* W  = (t == 1) ? Wq : (t == 2) ? Wk : Wv;
        const float* bb = (t == 1) ? bq : (t == 2) ? bk : bv;
        const float fw  = (t == 1) ? 1.0f   : 8.0f;
        const float fb  = (t == 1) ? 0.125f : 1.0f;
        float s = 0.0f;
        #pragma unroll
        for (int d = p*16; d < p*16 + 16; ++d)
            s += bp[d] * W[d*64 + j];
        red[tid] = s;
        __syncthreads();
        if (p == 0)
            g_fb[t*64 + j] =
                fw * (red[j] + red[64+j] + red[128+j] + red[192+j]) + fb * bb[j];
        __syncthreads();
    }
}

/* ------------------------------------------------------------------ */
/* K1: x,q,k,v = in @ fused.  512 thr, 64 rows/block, weights in regs */
/* ------------------------------------------------------------------ */
__global__ void __launch_bounds__(512) k_qkv(
    const float* __restrict__ inp,
    float* __restrict__ outK, float* __restrict__ outV)
{
    extern __shared__ float sm[];
    float* sW  = sm;          /* 2816 */
    float* sB  = sW + 2816;   /* 256  */
    float* sIn = sB + 256;    /* 704  */
    const int tid = threadIdx.x;
    const int row0 = blockIdx.x * 64;

    for (int i = tid; i < 2816; i += 512) sW[i] = g_fw[i];
    if (tid < 256) sB[tid] = g_fb[tid];
    for (int i = tid; i < 704; i += 512) sIn[i] = inp[(size_t)row0*11 + i];
    __syncthreads();

    const int j = tid & 63, rb = (tid >> 6) * 8;
    float wx[11], wq[11], wk[11], wv[11];
    #pragma unroll
    for (int i = 0; i < 11; ++i) {
        wx[i] = sW[i*64 + j];
        wq[i] = sW[704  + i*64 + j];
        wk[i] = sW[1408 + i*64 + j];
        wv[i] = sW[2112 + i*64 + j];
    }
    float ax[8], aq[8], ak[8], av[8];
    #pragma unroll
    for (int r = 0; r < 8; ++r) {
        ax[r] = sB[j]; aq[r] = sB[64+j]; ak[r] = sB[128+j]; av[r] = sB[192+j];
    }
    #pragma unroll
    for (int i = 0; i < 11; ++i) {
        #pragma unroll
        for (int r = 0; r < 8; ++r) {
            float in = sIn[(rb+r)*11 + i];
            ax[r] += in * wx[i];
            aq[r] += in * wq[i];
            ak[r] += in * wk[i];
            av[r] += in * wv[i];
        }
    }
    #pragma unroll
    for (int r = 0; r < 8; ++r) {
        size_t n = (size_t)(row0 + rb + r) * 64 + j;
        g_x[n]  = ax[r];
        g_q[n]  = aq[r];
        outK[n] = ak[r];
        outV[n] = av[r];
    }
}

/* ------------------------------------------------------------------ */
/* K2: causal attention, causal loop bounds, balanced warp mapping.   */
/* ------------------------------------------------------------------ */
template<int NC>
__device__ __forceinline__ void score_nc(
    const float* __restrict__ sKt, const float* __restrict__ sQ,
    int mbase, int lane, float (&sc)[5][5])
{
    #pragma unroll 2
    for (int i = 0; i < 64; ++i) {
        float kv[NC];
        #pragma unroll
        for (int c = 0; c < NC; ++c) kv[c] = sKt[i*161 + c*32 + lane];
        #pragma unroll
        for (int k = 0; k < 5; ++k) {
            float qi = sQ[(mbase+k)*64 + i];
            #pragma unroll
            for (int c = 0; c < NC; ++c) sc[k][c] += qi * kv[c];
        }
    }
}

__global__ void __launch_bounds__(256) k_attn(
    const float* __restrict__ Kin, const float* __restrict__ Vin,
    float* __restrict__ attnOut)
{
    extern __shared__ float sm[];
    float* sKt = sm;             /* 64 x 161 = 10304; reused as sA */
    float* sV  = sKt + 10304;    /* 160 x 64 = 10240 */
    float* sQ  = sV  + 10240;    /* 40 x 64  = 2560  */
    float* sA  = sKt;

    const int tid  = threadIdx.x;
    const int lane = tid & 31;
    const int w    = tid >> 5;
    const int part = blockIdx.x >> 2;
    const int quad = blockIdx.x & 3;
    const int r    = (w < 4) ? w : 11 - w;
    const int mbase = 5 * r;
    const int tmax  = quad + 20*r + 16;
    const int nc    = (tmax >> 5) + 1;

    const float4* Kg4 = (const float4*)(Kin + (size_t)part*160*64);
    const float4* Vg4 = (const float4*)(Vin + (size_t)part*160*64);
    float4* sV4 = (float4*)sV;

    for (int idx = tid; idx < 160*16; idx += 256) {
        int s = idx >> 4, i4 = (idx & 15) * 4;
        float4 kk = Kg4[idx];
        sKt[(i4+0)*161 + s] = kk.x;
        sKt[(i4+1)*161 + s] = kk.y;
        sKt[(i4+2)*161 + s] = kk.z;
        sKt[(i4+3)*161 + s] = kk.w;
        sV4[idx] = Vg4[idx];
    }
    for (int idx = tid; idx < 40*16; idx += 256) {
        int m = idx >> 4, i4 = idx & 15;
        int row = part*160 + quad + 4*m;
        ((float4*)(sQ + m*64))[i4] = ((const float4*)(g_q + (size_t)row*64))[i4];
    }
    __syncthreads();

    float sc[5][5];
    #pragma unroll
    for (int k = 0; k < 5; ++k)
        #pragma unroll
        for (int c = 0; c < 5; ++c) sc[k][c] = 0.0f;

    switch (nc) {
        case 1: score_nc<1>(sKt, sQ, mbase, lane, sc); break;
        case 2: score_nc<2>(sKt, sQ, mbase, lane, sc); break;
        case 3: score_nc<3>(sKt, sQ, mbase, lane, sc); break;
        case 4: score_nc<4>(sKt, sQ, mbase, lane, sc); break;
        default: score_nc<5>(sKt, sQ, mbase, lane, sc); break;
    }

    #pragma unroll
    for (int k = 0; k < 5; ++k) {
        const int t = quad + 4*(mbase + k);
        float mval = -3.4e38f;
        #pragma unroll
        for (int c = 0; c < 5; ++c) {
            int s = c*32 + lane;
            if (c < nc && s <= t) mval = fmaxf(mval, sc[k][c]);
        }
        #pragma unroll
        for (int o = 16; o; o >>= 1) mval = fmaxf(mval, __shfl_xor_sync(0xffffffffu, mval, o));
        float sum = 0.0f;
        #pragma unroll
        for (int c = 0; c < 5; ++c) {
            int s = c*32 + lane;
            float p = (c < nc && s <= t) ? expf(sc[k][c] - mval) : 0.0f;
            sc[k][c] = p;
            sum += p;
        }
        #pragma unroll
        for (int o = 16; o; o >>= 1) sum += __shfl_xor_sync(0xffffffffu, sum, o);
        float inv = 1.0f / sum;
        float* arow = attnOut + (size_t)(part*160 + t)*160;
        #pragma unroll
        for (int c = 0; c < 5; ++c) {
            if (c < nc) {
                sc[k][c] *= inv;
                arow[c*32 + lane] = sc[k][c];
            } else {
                arow[c*32 + lane] = 0.0f;
            }
        }
    }

    __syncthreads();

    #pragma unroll
    for (int k = 0; k < 5; ++k) {
        #pragma unroll
        for (int c = 0; c < 5; ++c)
            if (c < nc) sA[(mbase+k)*160 + c*32 + lane] = sc[k][c];
    }
    __syncwarp();

    const float2* sV2 = (const float2*)sV;
    float2 acc[5];
    #pragma unroll
    for (int k = 0; k < 5; ++k) acc[k] = make_float2(0.f, 0.f);

    const int send = (tmax + 4) & ~3;
    for (int s = 0; s < send; s += 4) {
        float4 a[5];
        #pragma unroll
        for (int k = 0; k < 5; ++k)
            a[k] = *(const float4*)(sA + (mbase+k)*160 + s);
        float2 v0 = sV2[(s+0)*32 + lane];
        float2 v1 = sV2[(s+1)*32 + lane];
        float2 v2 = sV2[(s+2)*32 + lane];
        float2 v3 = sV2[(s+3)*32 + lane];
        #pragma unroll
        for (int k = 0; k < 5; ++k) {
            acc[k].x += a[k].x*v0.x + a[k].y*v1.x + a[k].z*v2.x + a[k].w*v3.x;
            acc[k].y += a[k].x*v0.y + a[k].y*v1.y + a[k].z*v2.y + a[k].w*v3.y;
        }
    }
    #pragma unroll
    for (int k = 0; k < 5; ++k) {
        const int t = quad + 4*(mbase + k);
        size_t n = (size_t)part*160 + t;
        ((float2*)(g_z + n*64))[lane] = acc[k];
    }
}

/* ------------------------------------------------------------------ */
/* K3: persistent epilogue (R5 best-measured version, verbatim).      */
/* ------------------------------------------------------------------ */
__global__ void __launch_bounds__(512) k_epi(
    const float* __restrict__ Wo, const float* __restrict__ bo,
    const float* __restrict__ ln1g, const float* __restrict__ ln1b,
    const float* __restrict__ W1, const float* __restrict__ b1,
    const float* __restrict__ W2, const float* __restrict__ b2,
    const float* __restrict__ ln2g, const float* __restrict__ ln2b,
    const float* __restrict__ Wf, const float* __restrict__ bf,
    float* __restrict__ outR, float* __restrict__ outP, float* __restrict__ outP2)
{
    extern __shared__ float sm[];
    float* sWo = sm;            /* 4096  */
    float* sW1 = sWo + 4096;    /* 16384 */
    float* sW2 = sW1 + 16384;   /* 16384 */
    float* sC  = sW2 + 16384;   /* 704 */
    float* sO1 = sC  + 704;     /* 2048 */
    float* sH  = sO1 + 2048;    /* 8192 (also Wo partials 4x2048) */
    float* sP  = sH  + 8192;    /* 4096: FFN2 partials 2x2048 */

    const int tid = threadIdx.x;

    for (int i = tid; i < 1024; i += 512) ((float4*)sWo)[i] = ((const float4*)Wo)[i];
    for (int i = tid; i < 4096; i += 512) {
        ((float4*)sW1)[i] = ((const float4*)W1)[i];
        ((float4*)sW2)[i] = ((const float4*)W2)[i];
    }
    if (tid < 64) {
        sC[tid]     = bo[tid];
        sC[320+tid] = b2[tid];
        sC[384+tid] = ln1g[tid];
        sC[448+tid] = ln1b[tid];
        sC[512+tid] = ln2g[tid];
        sC[576+tid] = ln2b[tid];
        sC[640+tid] = Wf[tid];
    }
    if (tid < 256) sC[64 + tid] = b1[tid];
    const float bfv = bf[0];
    __syncthreads();

    for (int tile = blockIdx.x; tile < NROW/32; tile += gridDim.x) {
        const int row0 = tile * 32;

        /* (1) Wo: 4-way K-split, 4 rows x 4 cols */
        {
            const int isp = tid >> 7;
            const int t1  = tid & 127;
            const int cq  = t1 & 15;
            const int rq  = t1 >> 4;
            float4 acc0 = {0,0,0,0}, acc1 = {0,0,0,0}, acc2 = {0,0,0,0}, acc3 = {0,0,0,0};
            #pragma unroll
            for (int i4 = isp*4; i4 < isp*4 + 4; ++i4) {
                float4 w0 = ((const float4*)(sWo + (i4*4+0)*64))[cq];
                float4 w1 = ((const float4*)(sWo + (i4*4+1)*64))[cq];
                float4 w2 = ((const float4*)(sWo + (i4*4+2)*64))[cq];
                float4 w3 = ((const float4*)(sWo + (i4*4+3)*64))[cq];
                float4 a0 = ((const float4*)(g_z + (size_t)(row0 + 4*rq+0)*64))[i4];
                float4 a1 = ((const float4*)(g_z + (size_t)(row0 + 4*rq+1)*64))[i4];
                float4 a2 = ((const float4*)(g_z + (size_t)(row0 + 4*rq+2)*64))[i4];
                float4 a3 = ((const float4*)(g_z + (size_t)(row0 + 4*rq+3)*64))[i4];
                fma4(acc0, a0.x, w0); fma4(acc0, a0.y, w1); fma4(acc0, a0.z, w2); fma4(acc0, a0.w, w3);
                fma4(acc1, a1.x, w0); fma4(acc1, a1.y, w1); fma4(acc1, a1.z, w2); fma4(acc1, a1.w, w3);
                fma4(acc2, a2.x, w0); fma4(acc2, a2.y, w1); fma4(acc2, a2.z, w2); fma4(acc2, a2.w, w3);
                fma4(acc3, a3.x, w0); fma4(acc3, a3.y, w1); fma4(acc3, a3.z, w2); fma4(acc3, a3.w, w3);
            }
            float4* dst = (float4*)(sH + isp*2048);
            dst[(4*rq+0)*16 + cq] = acc0;
            dst[(4*rq+1)*16 + cq] = acc1;
            dst[(4*rq+2)*16 + cq] = acc2;
            dst[(4*rq+3)*16 + cq] = acc3;
        }
        __syncthreads();
        /* (2) reduce + bias + residual + LN1 -> sO1 */
        {
            const float4* p = (const float4*)sH;
            float4 v = p[tid];
            float4 v1 = p[512 + tid], v2 = p[1024 + tid], v3 = p[1536 + tid];
            const int row = tid >> 4, c4 = tid & 15;
            float4 b = ((const float4*)sC)[c4];
            float4 rx = ((const float4*)(g_x + (size_t)(row0 + row)*64))[c4];
            v.x += v1.x + v2.x + v3.x + b.x + rx.x;
            v.y += v1.y + v2.y + v3.y + b.y + rx.y;
            v.z += v1.z + v2.z + v3.z + b.z + rx.z;
            v.w += v1.w + v2.w + v3.w + b.w + rx.w;
            float s = v.x + v.y + v.z + v.w;
            #pragma unroll
            for (int o = 8; o; o >>= 1) s += __shfl_xor_sync(0xffffffffu, s, o);
            float mu = s * (1.0f/64.0f);
            float4 d = {v.x-mu, v.y-mu, v.z-mu, v.w-mu};
            float q = d.x*d.x + d.y*d.y + d.z*d.z + d.w*d.w;
            #pragma unroll
            for (int o = 8; o; o >>= 1) q += __shfl_xor_sync(0xffffffffu, q, o);
            float is = rsqrtf(q * (1.0f/64.0f) + 1e-6f);
            float4 g = ((const float4*)(sC + 384))[c4];
            float4 bb = ((const float4*)(sC + 448))[c4];
            float4 o1 = {g.x*d.x*is + bb.x, g.y*d.y*is + bb.y,
                         g.z*d.z*is + bb.z, g.w*d.w*is + bb.w};
            ((float4*)sO1)[tid] = o1;
        }
        __syncthreads();

        /* (3) FFN1 4x4 + relu */
        {
            const int cq = tid & 63;
            const int rq = tid >> 6;
            float4 b = ((const float4*)(sC + 64))[cq];
            float4 acc0 = b, acc1 = b, acc2 = b, acc3 = b;
            #pragma unroll 4
            for (int i4 = 0; i4 < 16; ++i4) {
                float4 w0 = ((const float4*)(sW1 + (i4*4+0)*256))[cq];
                float4 w1 = ((const float4*)(sW1 + (i4*4+1)*256))[cq];
                float4 w2 = ((const float4*)(sW1 + (i4*4+2)*256))[cq];
                float4 w3 = ((const float4*)(sW1 + (i4*4+3)*256))[cq];
                float4 a0 = ((const float4*)(sO1 + (4*rq+0)*64))[i4];
                float4 a1 = ((const float4*)(sO1 + (4*rq+1)*64))[i4];
                float4 a2 = ((const float4*)(sO1 + (4*rq+2)*64))[i4];
                float4 a3 = ((const float4*)(sO1 + (4*rq+3)*64))[i4];
                fma4(acc0, a0.x, w0); fma4(acc0, a0.y, w1); fma4(acc0, a0.z, w2); fma4(acc0, a0.w, w3);
                fma4(acc1, a1.x, w0); fma4(acc1, a1.y, w1); fma4(acc1, a1.z, w2); fma4(acc1, a1.w, w3);
                fma4(acc2, a2.x, w0); fma4(acc2, a2.y, w1); fma4(acc2, a2.z, w2); fma4(acc2, a2.w, w3);
                fma4(acc3, a3.x, w0); fma4(acc3, a3.y, w1); fma4(acc3, a3.z, w2); fma4(acc3, a3.w, w3);
            }
            acc0.x = fmaxf(acc0.x, 0.f); acc0.y = fmaxf(acc0.y, 0.f);
            acc0.z = fmaxf(acc0.z, 0.f); acc0.w = fmaxf(acc0.w, 0.f);
            acc1.x = fmaxf(acc1.x, 0.f); acc1.y = fmaxf(acc1.y, 0.f);
            acc1.z = fmaxf(acc1.z, 0.f); acc1.w = fmaxf(acc1.w, 0.f);
            acc2.x = fmaxf(acc2.x, 0.f); acc2.y = fmaxf(acc2.y, 0.f);
            acc2.z = fmaxf(acc2.z, 0.f); acc2.w = fmaxf(acc2.w, 0.f);
            acc3.x = fmaxf(acc3.x, 0.f); acc3.y = fmaxf(acc3.y, 0.f);
            acc3.z = fmaxf(acc3.z, 0.f); acc3.w = fmaxf(acc3.w, 0.f);
            ((float4*)(sH + (4*rq+0)*256))[cq] = acc0;
            ((float4*)(sH + (4*rq+1)*256))[cq] = acc1;
            ((float4*)(sH + (4*rq+2)*256))[cq] = acc2;
            ((float4*)(sH + (4*rq+3)*256))[cq] = acc3;
        }
        __syncthreads();

        /* (4) FFN2: 2-way K-split, 2 rows x 4 cols */
        {
            const int isp = tid >> 8;
            const int t2  = tid & 255;
            const int cq  = t2 & 15;
            const int rq  = t2 >> 4;
            float4 acc0 = {0,0,0,0}, acc1 = {0,0,0,0};
            #pragma unroll 4
            for (int i4 = isp*32; i4 < isp*32 + 32; ++i4) {
                float4 w0 = ((const float4*)(sW2 + (i4*4+0)*64))[cq];
                float4 w1 = ((const float4*)(sW2 + (i4*4+1)*64))[cq];
                float4 w2 = ((const float4*)(sW2 + (i4*4+2)*64))[cq];
                float4 w3 = ((const float4*)(sW2 + (i4*4+3)*64))[cq];
                float4 a0 = ((const float4*)(sH + (2*rq+0)*256))[i4];
                float4 a1 = ((const float4*)(sH + (2*rq+1)*256))[i4];
                fma4(acc0, a0.x, w0); fma4(acc0, a0.y, w1); fma4(acc0, a0.z, w2); fma4(acc0, a0.w, w3);
                fma4(acc1, a1.x, w0); fma4(acc1, a1.y, w1); fma4(acc1, a1.z, w2); fma4(acc1, a1.w, w3);
            }
            float4* dst = (float4*)(sP + isp*2048);
            dst[(2*rq+0)*16 + cq] = acc0;
            dst[(2*rq+1)*16 + cq] = acc1;
        }
        __syncthreads();
        /* (5) reduce + bias + residual + LN2 + outputs */
        {
            const float4* p = (const float4*)sP;
            float4 v = p[tid];
            float4 v1 = p[512 + tid];
            const int row = tid >> 4, c4 = tid & 15;
            float4 b = ((const float4*)(sC + 320))[c4];
            float4 rs = ((const float4*)sO1)[tid];
            v.x += v1.x + b.x + rs.x;
            v.y += v1.y + b.y + rs.y;
            v.z += v1.z + b.z + rs.z;
            v.w += v1.w + b.w + rs.w;
            float s = v.x + v.y + v.z + v.w;
            #pragma unroll
            for (int o = 8; o; o >>= 1) s += __shfl_xor_sync(0xffffffffu, s, o);
            float mu = s * (1.0f/64.0f);
            float4 d = {v.x-mu, v.y-mu, v.z-mu, v.w-mu};
            float q = d.x*d.x + d.y*d.y + d.z*d.z + d.w*d.w;
            #pragma unroll
            for (int o = 8; o; o >>= 1) q += __shfl_xor_sync(0xffffffffu, q, o);
            float is = rsqrtf(q * (1.0f/64.0f) + 1e-6f);
            float4 g = ((const float4*)(sC + 512))[c4];
            float4 bb = ((const float4*)(sC + 576))[c4];
            float4 rv = {g.x*d.x*is + bb.x, g.y*d.y*is + bb.y,
                         g.z*d.z*is + bb.z, g.w*d.w*is + bb.w};
            const size_t n = (size_t)row0 + row;
            ((float4*)(outR + n*64))[c4] = rv;
            float4 wf = ((const float4*)(sC + 640))[c4];
            float pp = rv.x*wf.x + rv.y*wf.y + rv.z*wf.z + rv.w*wf.w;
            #pragma unroll
            for (int o = 8; o; o >>= 1) pp += __shfl_xor_sync(0xffffffffu, pp, o);
            if (c4 == 0) {
                float pv = pp + bfv;
                outP[n]  = pv;
                outP2[n] = pv;
            }
        }
        __syncthreads();
    }
}

/* ------------------------------------------------------------------ */
extern "C" void kernel_launch(void* const* d_in, const int* in_sizes, int n_in,
                              void* d_out, int out_size)
{
    (void)in_sizes; (void)n_in; (void)out_size;
    const float* inputs = (const float*)d_in[0];
    const float* Wp  = (const float*)d_in[2];
    const float* bp  = (const float*)d_in[3];
    const float* Wq  = (const float*)d_in[4];
    const float* bq  = (const float*)d_in[5];
    const float* Wk  = (const float*)d_in[6];
    const float* bk  = (const float*)d_in[7];
    const float* Wv  = (const float*)d_in[8];
    const float* bv  = (const float*)d_in[9];
    const float* Wo  = (const float*)d_in[10];
    const float* bo  = (const float*)d_in[11];
    const float* l1g = (const float*)d_in[12];
    const float* l1b = (const float*)d_in[13];
    const float* W1  = (const float*)d_in[14];
    const float* b1  = (const float*)d_in[15];
    const float* W2  = (const float*)d_in[16];
    const float* b2  = (const float*)d_in[17];
    const float* l2g = (const float*)d_in[18];
    const float* l2b = (const float*)d_in[19];
    const float* Wf  = (const float*)d_in[20];
    const float* bf  = (const float*)d_in[21];
    float* out = (float*)d_out;

    const size_t sm1 = (size_t)(2816 + 256 + 704) * 4;                          /* ~15 KB  */
    const size_t sm2 = (size_t)(10304 + 10240 + 2560) * 4;                      /* ~92 KB  */
    const size_t sm3 = (size_t)(4096 + 16384 + 16384 + 704 + 2048 + 8192 + 4096) * 4; /* ~203 KB */

    cudaFuncSetAttribute(k_qkv,  cudaFuncAttributeMaxDynamicSharedMemorySize, (int)sm1);
    cudaFuncSetAttribute(k_attn, cudaFuncAttributeMaxDynamicSharedMemorySize, (int)sm2);
    cudaFuncSetAttribute(k_epi,  cudaFuncAttributeMaxDynamicSharedMemorySize, (int)sm3);

    k_fold<<<35, 256>>>(Wp, bp, Wq, bq, Wk, bk, Wv, bv);
    k_qkv<<<NROW/64, 512, sm1>>>(inputs, out + OFF_K, out + OFF_V);
    k_attn<<<NPART*4, 256, sm2>>>(out + OFF_K, out + OFF_V, out + OFF_ATTN);
    k_epi<<<148, 512, sm3>>>(Wo, bo, l1g, l1b, W1, b1, W2, b2, l2g, l2b, Wf, bf,
                             out + OFF_R, out + OFF_PRED, out + OFF_PRED2);
}

// round 14
// speedup vs baseline: 1.4592x; 1.0552x over previous
#include <cuda_runtime.h>

#define B_ 8
#define P_ 10
#define S_ 160
#define FX_ 11
#define D_ 64
#define DFF_ 256
#define NROW (B_*P_*S_)   /* 12800 */
#define NPART (B_*P_)     /* 80 */

/* output layout (tuple order): pred, pred_resampl, K, V, R, attn_weights */
#define OFF_PRED  0
#define OFF_PRED2 (NROW)
#define OFF_K     (2*NROW)
#define OFF_V     (OFF_K + NROW*D_)
#define OFF_R     (OFF_V + NROW*D_)
#define OFF_ATTN  (OFF_R + NROW*D_)

/* scratch (no cudaMalloc allowed) */
__device__ float g_x[NROW*D_];
__device__ float g_q[NROW*D_];
__device__ float g_z[NROW*D_];
__device__ float g_fw[4*704];   /* fused 11x64 weights: x,q,k,v */
__device__ float g_fb[4*64];    /* fused biases */

__device__ __forceinline__ void fma4(float4& acc, float s, const float4& v) {
    acc.x += s * v.x; acc.y += s * v.y; acc.z += s * v.z; acc.w += s * v.w;
}

/* ------------------------------------------------------------------ */
/* K0: fold Wp into Wq/Wk/Wv. PARALLEL: 35 blocks.                    */
/* ------------------------------------------------------------------ */
__global__ void __launch_bounds__(256) k_fold(
    const float* __restrict__ Wp, const float* __restrict__ bp,
    const float* __restrict__ Wq, const float* __restrict__ bq,
    const float* __restrict__ Wk, const float* __restrict__ bk,
    const float* __restrict__ Wv, const float* __restrict__ bv)
{
    __shared__ float red[256];
    const int b = blockIdx.x, tid = threadIdx.x;

    if (b == 0) {
        for (int i = tid; i < 704; i += 256) g_fw[i] = 8.0f * Wp[i];
        if (tid < 64) g_fb[tid] = 8.0f * bp[tid];
        return;
    }
    const int j = tid & 63, p = tid >> 6;

    if (b <= 33) {
        const int t = (b - 1) / 11 + 1;     /* 1=q, 2=k, 3=v */
        const int i = (b - 1) % 11;
        const float* W  = (t == 1) ? Wq : (t == 2) ? Wk : Wv;
        const float fw  = (t == 1) ? 1.0f : 8.0f;
        float s = 0.0f;
        #pragma unroll
        for (int d = p*16; d < p*16 + 16; ++d)
            s += Wp[i*64 + d] * W[d*64 + j];
        red[tid] = s;
        __syncthreads();
        if (p == 0)
            g_fw[t*704 + i*64 + j] =
                fw * (red[j] + red[64+j] + red[128+j] + red[192+j]);
        return;
    }

    /* b == 34: fused biases for q,k,v */
    #pragma unroll
    for (int t = 1; t <= 3; ++t) {
        const float* W  = (t == 1) ? Wq : (t == 2) ? Wk : Wv;
        const float* bb = (t == 1) ? bq : (t == 2) ? bk : bv;
        const float fw  = (t == 1) ? 1.0f   : 8.0f;
        const float fb  = (t == 1) ? 0.125f : 1.0f;
        float s = 0.0f;
        #pragma unroll
        for (int d = p*16; d < p*16 + 16; ++d)
            s += bp[d] * W[d*64 + j];
        red[tid] = s;
        __syncthreads();
        if (p == 0)
            g_fb[t*64 + j] =
                fw * (red[j] + red[64+j] + red[128+j] + red[192+j]) + fb * bb[j];
        __syncthreads();
    }
}

/* ------------------------------------------------------------------ */
/* K1: x,q,k,v = in @ fused.  512 thr, 64 rows/block, weights in regs */
/* ------------------------------------------------------------------ */
__global__ void __launch_bounds__(512) k_qkv(
    const float* __restrict__ inp,
    float* __restrict__ outK, float* __restrict__ outV)
{
    extern __shared__ float sm[];
    float* sW  = sm;          /* 2816 */
    float* sB  = sW + 2816;   /* 256  */
    float* sIn = sB + 256;    /* 704  */
    const int tid = threadIdx.x;
    const int row0 = blockIdx.x * 64;

    for (int i = tid; i < 2816; i += 512) sW[i] = g_fw[i];
    if (tid < 256) sB[tid] = g_fb[tid];
    for (int i = tid; i < 704; i += 512) sIn[i] = inp[(size_t)row0*11 + i];
    __syncthreads();

    const int j = tid & 63, rb = (tid >> 6) * 8;
    float wx[11], wq[11], wk[11], wv[11];
    #pragma unroll
    for (int i = 0; i < 11; ++i) {
        wx[i] = sW[i*64 + j];
        wq[i] = sW[704  + i*64 + j];
        wk[i] = sW[1408 + i*64 + j];
        wv[i] = sW[2112 + i*64 + j];
    }
    float ax[8], aq[8], ak[8], av[8];
    #pragma unroll
    for (int r = 0; r < 8; ++r) {
        ax[r] = sB[j]; aq[r] = sB[64+j]; ak[r] = sB[128+j]; av[r] = sB[192+j];
    }
    #pragma unroll
    for (int i = 0; i < 11; ++i) {
        #pragma unroll
        for (int r = 0; r < 8; ++r) {
            float in = sIn[(rb+r)*11 + i];
            ax[r] += in * wx[i];
            aq[r] += in * wq[i];
            ak[r] += in * wk[i];
            av[r] += in * wv[i];
        }
    }
    #pragma unroll
    for (int r = 0; r < 8; ++r) {
        size_t n = (size_t)(row0 + rb + r) * 64 + j;
        g_x[n]  = ax[r];
        g_q[n]  = aq[r];
        outK[n] = ak[r];
        outV[n] = av[r];
    }
}

/* ------------------------------------------------------------------ */
/* K2: causal attention, causal loop bounds, balanced warp mapping.   */
/* ------------------------------------------------------------------ */
template<int NC>
__device__ __forceinline__ void score_nc(
    const float* __restrict__ sKt, const float* __restrict__ sQ,
    int mbase, int lane, float (&sc)[5][5])
{
    #pragma unroll 2
    for (int i = 0; i < 64; ++i) {
        float kv[NC];
        #pragma unroll
        for (int c = 0; c < NC; ++c) kv[c] = sKt[i*161 + c*32 + lane];
        #pragma unroll
        for (int k = 0; k < 5; ++k) {
            float qi = sQ[(mbase+k)*64 + i];
            #pragma unroll
            for (int c = 0; c < NC; ++c) sc[k][c] += qi * kv[c];
        }
    }
}

__global__ void __launch_bounds__(256) k_attn(
    const float* __restrict__ Kin, const float* __restrict__ Vin,
    float* __restrict__ attnOut)
{
    extern __shared__ float sm[];
    float* sKt = sm;             /* 64 x 161 = 10304; reused as sA */
    float* sV  = sKt + 10304;    /* 160 x 64 = 10240 */
    float* sQ  = sV  + 10240;    /* 40 x 64  = 2560  */
    float* sA  = sKt;

    const int tid  = threadIdx.x;
    const int lane = tid & 31;
    const int w    = tid >> 5;
    const int part = blockIdx.x >> 2;
    const int quad = blockIdx.x & 3;
    const int r    = (w < 4) ? w : 11 - w;
    const int mbase = 5 * r;
    const int tmax  = quad + 20*r + 16;
    const int nc    = (tmax >> 5) + 1;

    const float4* Kg4 = (const float4*)(Kin + (size_t)part*160*64);
    const float4* Vg4 = (const float4*)(Vin + (size_t)part*160*64);
    float4* sV4 = (float4*)sV;

    for (int idx = tid; idx < 160*16; idx += 256) {
        int s = idx >> 4, i4 = (idx & 15) * 4;
        float4 kk = Kg4[idx];
        sKt[(i4+0)*161 + s] = kk.x;
        sKt[(i4+1)*161 + s] = kk.y;
        sKt[(i4+2)*161 + s] = kk.z;
        sKt[(i4+3)*161 + s] = kk.w;
        sV4[idx] = Vg4[idx];
    }
    for (int idx = tid; idx < 40*16; idx += 256) {
        int m = idx >> 4, i4 = idx & 15;
        int row = part*160 + quad + 4*m;
        ((float4*)(sQ + m*64))[i4] = ((const float4*)(g_q + (size_t)row*64))[i4];
    }
    __syncthreads();

    float sc[5][5];
    #pragma unroll
    for (int k = 0; k < 5; ++k)
        #pragma unroll
        for (int c = 0; c < 5; ++c) sc[k][c] = 0.0f;

    switch (nc) {
        case 1: score_nc<1>(sKt, sQ, mbase, lane, sc); break;
        case 2: score_nc<2>(sKt, sQ, mbase, lane, sc); break;
        case 3: score_nc<3>(sKt, sQ, mbase, lane, sc); break;
        case 4: score_nc<4>(sKt, sQ, mbase, lane, sc); break;
        default: score_nc<5>(sKt, sQ, mbase, lane, sc); break;
    }

    #pragma unroll
    for (int k = 0; k < 5; ++k) {
        const int t = quad + 4*(mbase + k);
        float mval = -3.4e38f;
        #pragma unroll
        for (int c = 0; c < 5; ++c) {
            int s = c*32 + lane;
            if (c < nc && s <= t) mval = fmaxf(mval, sc[k][c]);
        }
        #pragma unroll
        for (int o = 16; o; o >>= 1) mval = fmaxf(mval, __shfl_xor_sync(0xffffffffu, mval, o));
        float sum = 0.0f;
        #pragma unroll
        for (int c = 0; c < 5; ++c) {
            int s = c*32 + lane;
            float p = (c < nc && s <= t) ? expf(sc[k][c] - mval) : 0.0f;
            sc[k][c] = p;
            sum += p;
        }
        #pragma unroll
        for (int o = 16; o; o >>= 1) sum += __shfl_xor_sync(0xffffffffu, sum, o);
        float inv = 1.0f / sum;
        float* arow = attnOut + (size_t)(part*160 + t)*160;
        #pragma unroll
        for (int c = 0; c < 5; ++c) {
            if (c < nc) {
                sc[k][c] *= inv;
                arow[c*32 + lane] = sc[k][c];
            } else {
                arow[c*32 + lane] = 0.0f;
            }
        }
    }

    __syncthreads();

    #pragma unroll
    for (int k = 0; k < 5; ++k) {
        #pragma unroll
        for (int c = 0; c < 5; ++c)
            if (c < nc) sA[(mbase+k)*160 + c*32 + lane] = sc[k][c];
    }
    __syncwarp();

    const float2* sV2 = (const float2*)sV;
    float2 acc[5];
    #pragma unroll
    for (int k = 0; k < 5; ++k) acc[k] = make_float2(0.f, 0.f);

    const int send = (tmax + 4) & ~3;
    for (int s = 0; s < send; s += 4) {
        float4 a[5];
        #pragma unroll
        for (int k = 0; k < 5; ++k)
            a[k] = *(const float4*)(sA + (mbase+k)*160 + s);
        float2 v0 = sV2[(s+0)*32 + lane];
        float2 v1 = sV2[(s+1)*32 + lane];
        float2 v2 = sV2[(s+2)*32 + lane];
        float2 v3 = sV2[(s+3)*32 + lane];
        #pragma unroll
        for (int k = 0; k < 5; ++k) {
            acc[k].x += a[k].x*v0.x + a[k].y*v1.x + a[k].z*v2.x + a[k].w*v3.x;
            acc[k].y += a[k].x*v0.y + a[k].y*v1.y + a[k].z*v2.y + a[k].w*v3.y;
        }
    }
    #pragma unroll
    for (int k = 0; k < 5; ++k) {
        const int t = quad + 4*(mbase + k);
        size_t n = (size_t)part*160 + t;
        ((float2*)(g_z + n*64))[lane] = acc[k];
    }
}

/* ------------------------------------------------------------------ */
/* K3: persistent epilogue. FFN2 upgraded to 4-way K-split, 4x4       */
/* register blocking (2 B/FMA smem traffic, matching Wo/FFN1).        */
/* ------------------------------------------------------------------ */
__global__ void __launch_bounds__(512) k_epi(
    const float* __restrict__ Wo, const float* __restrict__ bo,
    const float* __restrict__ ln1g, const float* __restrict__ ln1b,
    const float* __restrict__ W1, const float* __restrict__ b1,
    const float* __restrict__ W2, const float* __restrict__ b2,
    const float* __restrict__ ln2g, const float* __restrict__ ln2b,
    const float* __restrict__ Wf, const float* __restrict__ bf,
    float* __restrict__ outR, float* __restrict__ outP, float* __restrict__ outP2)
{
    extern __shared__ float sm[];
    float* sWo = sm;            /* 4096  */
    float* sW1 = sWo + 4096;    /* 16384 */
    float* sW2 = sW1 + 16384;   /* 16384 */
    float* sC  = sW2 + 16384;   /* 704 */
    float* sO1 = sC  + 704;     /* 2048 */
    float* sH  = sO1 + 2048;    /* 8192 (also Wo partials 4x2048) */
    float* sP  = sH  + 8192;    /* 8192: FFN2 partials 4x2048 */

    const int tid = threadIdx.x;

    for (int i = tid; i < 1024; i += 512) ((float4*)sWo)[i] = ((const float4*)Wo)[i];
    for (int i = tid; i < 4096; i += 512) {
        ((float4*)sW1)[i] = ((const float4*)W1)[i];
        ((float4*)sW2)[i] = ((const float4*)W2)[i];
    }
    if (tid < 64) {
        sC[tid]     = bo[tid];
        sC[320+tid] = b2[tid];
        sC[384+tid] = ln1g[tid];
        sC[448+tid] = ln1b[tid];
        sC[512+tid] = ln2g[tid];
        sC[576+tid] = ln2b[tid];
        sC[640+tid] = Wf[tid];
    }
    if (tid < 256) sC[64 + tid] = b1[tid];
    const float bfv = bf[0];
    __syncthreads();

    /* shared thread-role decode for the split stages */
    const int isp = tid >> 7;          /* 0..3 K-split */
    const int t1  = tid & 127;
    const int cq  = t1 & 15;           /* col-quad */
    const int rq  = t1 >> 4;           /* 0..7 -> rows 4rq.. */

    for (int tile = blockIdx.x; tile < NROW/32; tile += gridDim.x) {
        const int row0 = tile * 32;

        /* (1) Wo: 4-way K-split, 4 rows x 4 cols */
        {
            float4 acc0 = {0,0,0,0}, acc1 = {0,0,0,0}, acc2 = {0,0,0,0}, acc3 = {0,0,0,0};
            #pragma unroll
            for (int i4 = isp*4; i4 < isp*4 + 4; ++i4) {
                float4 w0 = ((const float4*)(sWo + (i4*4+0)*64))[cq];
                float4 w1 = ((const float4*)(sWo + (i4*4+1)*64))[cq];
                float4 w2 = ((const float4*)(sWo + (i4*4+2)*64))[cq];
                float4 w3 = ((const float4*)(sWo + (i4*4+3)*64))[cq];
                float4 a0 = ((const float4*)(g_z + (size_t)(row0 + 4*rq+0)*64))[i4];
                float4 a1 = ((const float4*)(g_z + (size_t)(row0 + 4*rq+1)*64))[i4];
                float4 a2 = ((const float4*)(g_z + (size_t)(row0 + 4*rq+2)*64))[i4];
                float4 a3 = ((const float4*)(g_z + (size_t)(row0 + 4*rq+3)*64))[i4];
                fma4(acc0, a0.x, w0); fma4(acc0, a0.y, w1); fma4(acc0, a0.z, w2); fma4(acc0, a0.w, w3);
                fma4(acc1, a1.x, w0); fma4(acc1, a1.y, w1); fma4(acc1, a1.z, w2); fma4(acc1, a1.w, w3);
                fma4(acc2, a2.x, w0); fma4(acc2, a2.y, w1); fma4(acc2, a2.z, w2); fma4(acc2, a2.w, w3);
                fma4(acc3, a3.x, w0); fma4(acc3, a3.y, w1); fma4(acc3, a3.z, w2); fma4(acc3, a3.w, w3);
            }
            float4* dst = (float4*)(sH + isp*2048);
            dst[(4*rq+0)*16 + cq] = acc0;
            dst[(4*rq+1)*16 + cq] = acc1;
            dst[(4*rq+2)*16 + cq] = acc2;
            dst[(4*rq+3)*16 + cq] = acc3;
        }
        __syncthreads();
        /* (2) reduce + bias + residual + LN1 -> sO1 */
        {
            const float4* p = (const float4*)sH;
            float4 v = p[tid];
            float4 v1 = p[512 + tid], v2 = p[1024 + tid], v3 = p[1536 + tid];
            const int row = tid >> 4, c4 = tid & 15;
            float4 b = ((const float4*)sC)[c4];
            float4 rx = ((const float4*)(g_x + (size_t)(row0 + row)*64))[c4];
            v.x += v1.x + v2.x + v3.x + b.x + rx.x;
            v.y += v1.y + v2.y + v3.y + b.y + rx.y;
            v.z += v1.z + v2.z + v3.z + b.z + rx.z;
            v.w += v1.w + v2.w + v3.w + b.w + rx.w;
            float s = v.x + v.y + v.z + v.w;
            #pragma unroll
            for (int o = 8; o; o >>= 1) s += __shfl_xor_sync(0xffffffffu, s, o);
            float mu = s * (1.0f/64.0f);
            float4 d = {v.x-mu, v.y-mu, v.z-mu, v.w-mu};
            float q = d.x*d.x + d.y*d.y + d.z*d.z + d.w*d.w;
            #pragma unroll
            for (int o = 8; o; o >>= 1) q += __shfl_xor_sync(0xffffffffu, q, o);
            float is = rsqrtf(q * (1.0f/64.0f) + 1e-6f);
            float4 g = ((const float4*)(sC + 384))[c4];
            float4 bb = ((const float4*)(sC + 448))[c4];
            float4 o1 = {g.x*d.x*is + bb.x, g.y*d.y*is + bb.y,
                         g.z*d.z*is + bb.z, g.w*d.w*is + bb.w};
            ((float4*)sO1)[tid] = o1;
        }
        __syncthreads();

        /* (3) FFN1 4x4 + relu */
        {
            const int cqf = tid & 63;
            const int rqf = tid >> 6;
            float4 b = ((const float4*)(sC + 64))[cqf];
            float4 acc0 = b, acc1 = b, acc2 = b, acc3 = b;
            #pragma unroll 4
            for (int i4 = 0; i4 < 16; ++i4) {
                float4 w0 = ((const float4*)(sW1 + (i4*4+0)*256))[cqf];
                float4 w1 = ((const float4*)(sW1 + (i4*4+1)*256))[cqf];
                float4 w2 = ((const float4*)(sW1 + (i4*4+2)*256))[cqf];
                float4 w3 = ((const float4*)(sW1 + (i4*4+3)*256))[cqf];
                float4 a0 = ((const float4*)(sO1 + (4*rqf+0)*64))[i4];
                float4 a1 = ((const float4*)(sO1 + (4*rqf+1)*64))[i4];
                float4 a2 = ((const float4*)(sO1 + (4*rqf+2)*64))[i4];
                float4 a3 = ((const float4*)(sO1 + (4*rqf+3)*64))[i4];
                fma4(acc0, a0.x, w0); fma4(acc0, a0.y, w1); fma4(acc0, a0.z, w2); fma4(acc0, a0.w, w3);
                fma4(acc1, a1.x, w0); fma4(acc1, a1.y, w1); fma4(acc1, a1.z, w2); fma4(acc1, a1.w, w3);
                fma4(acc2, a2.x, w0); fma4(acc2, a2.y, w1); fma4(acc2, a2.z, w2); fma4(acc2, a2.w, w3);
                fma4(acc3, a3.x, w0); fma4(acc3, a3.y, w1); fma4(acc3, a3.z, w2); fma4(acc3, a3.w, w3);
            }
            acc0.x = fmaxf(acc0.x, 0.f); acc0.y = fmaxf(acc0.y, 0.f);
            acc0.z = fmaxf(acc0.z, 0.f); acc0.w = fmaxf(acc0.w, 0.f);
            acc1.x = fmaxf(acc1.x, 0.f); acc1.y = fmaxf(acc1.y, 0.f);
            acc1.z = fmaxf(acc1.z, 0.f); acc1.w = fmaxf(acc1.w, 0.f);
            acc2.x = fmaxf(acc2.x, 0.f); acc2.y = fmaxf(acc2.y, 0.f);
            acc2.z = fmaxf(acc2.z, 0.f); acc2.w = fmaxf(acc2.w, 0.f);
            acc3.x = fmaxf(acc3.x, 0.f); acc3.y = fmaxf(acc3.y, 0.f);
            acc3.z = fmaxf(acc3.z, 0.f); acc3.w = fmaxf(acc3.w, 0.f);
            ((float4*)(sH + (4*rqf+0)*256))[cqf] = acc0;
            ((float4*)(sH + (4*rqf+1)*256))[cqf] = acc1;
            ((float4*)(sH + (4*rqf+2)*256))[cqf] = acc2;
            ((float4*)(sH + (4*rqf+3)*256))[cqf] = acc3;
        }
        __syncthreads();

        /* (4) FFN2: 4-way K-split (16 i4 each), 4 rows x 4 cols */
        {
            float4 acc0 = {0,0,0,0}, acc1 = {0,0,0,0}, acc2 = {0,0,0,0}, acc3 = {0,0,0,0};
            #pragma unroll 4
            for (int i4 = isp*16; i4 < isp*16 + 16; ++i4) {
                float4 w0 = ((const float4*)(sW2 + (i4*4+0)*64))[cq];
                float4 w1 = ((const float4*)(sW2 + (i4*4+1)*64))[cq];
                float4 w2 = ((const float4*)(sW2 + (i4*4+2)*64))[cq];
                float4 w3 = ((const float4*)(sW2 + (i4*4+3)*64))[cq];
                float4 a0 = ((const float4*)(sH + (4*rq+0)*256))[i4];
                float4 a1 = ((const float4*)(sH + (4*rq+1)*256))[i4];
                float4 a2 = ((const float4*)(sH + (4*rq+2)*256))[i4];
                float4 a3 = ((const float4*)(sH + (4*rq+3)*256))[i4];
                fma4(acc0, a0.x, w0); fma4(acc0, a0.y, w1); fma4(acc0, a0.z, w2); fma4(acc0, a0.w, w3);
                fma4(acc1, a1.x, w0); fma4(acc1, a1.y, w1); fma4(acc1, a1.z, w2); fma4(acc1, a1.w, w3);
                fma4(acc2, a2.x, w0); fma4(acc2, a2.y, w1); fma4(acc2, a2.z, w2); fma4(acc2, a2.w, w3);
                fma4(acc3, a3.x, w0); fma4(acc3, a3.y, w1); fma4(acc3, a3.z, w2); fma4(acc3, a3.w, w3);
            }
            float4* dst = (float4*)(sP + isp*2048);
            dst[(4*rq+0)*16 + cq] = acc0;
            dst[(4*rq+1)*16 + cq] = acc1;
            dst[(4*rq+2)*16 + cq] = acc2;
            dst[(4*rq+3)*16 + cq] = acc3;
        }
        __syncthreads();
        /* (5) reduce 4 + bias + residual + LN2 + outputs */
        {
            const float4* p = (const float4*)sP;
            float4 v = p[tid];
            float4 v1 = p[512 + tid], v2 = p[1024 + tid], v3 = p[1536 + tid];
            const int row = tid >> 4, c4 = tid & 15;
            float4 b = ((const float4*)(sC + 320))[c4];
            float4 rs = ((const float4*)sO1)[tid];
            v.x += v1.x + v2.x + v3.x + b.x + rs.x;
            v.y += v1.y + v2.y + v3.y + b.y + rs.y;
            v.z += v1.z + v2.z + v3.z + b.z + rs.z;
            v.w += v1.w + v2.w + v3.w + b.w + rs.w;
            float s = v.x + v.y + v.z + v.w;
            #pragma unroll
            for (int o = 8; o; o >>= 1) s += __shfl_xor_sync(0xffffffffu, s, o);
            float mu = s * (1.0f/64.0f);
            float4 d = {v.x-mu, v.y-mu, v.z-mu, v.w-mu};
            float q = d.x*d.x + d.y*d.y + d.z*d.z + d.w*d.w;
            #pragma unroll
            for (int o = 8; o; o >>= 1) q += __shfl_xor_sync(0xffffffffu, q, o);
            float is = rsqrtf(q * (1.0f/64.0f) + 1e-6f);
            float4 g = ((const float4*)(sC + 512))[c4];
            float4 bb = ((const float4*)(sC + 576))[c4];
            float4 rv = {g.x*d.x*is + bb.x, g.y*d.y*is + bb.y,
                         g.z*d.z*is + bb.z, g.w*d.w*is + bb.w};
            const size_t n = (size_t)row0 + row;
            ((float4*)(outR + n*64))[c4] = rv;
            float4 wf = ((const float4*)(sC + 640))[c4];
            float pp = rv.x*wf.x + rv.y*wf.y + rv.z*wf.z + rv.w*wf.w;
            #pragma unroll
            for (int o = 8; o; o >>= 1) pp += __shfl_xor_sync(0xffffffffu, pp, o);
            if (c4 == 0) {
                float pv = pp + bfv;
                outP[n]  = pv;
                outP2[n] = pv;
            }
        }
        __syncthreads();
    }
}

/* ------------------------------------------------------------------ */
extern "C" void kernel_launch(void* const* d_in, const int* in_sizes, int n_in,
                              void* d_out, int out_size)
{
    (void)in_sizes; (void)n_in; (void)out_size;
    const float* inputs = (const float*)d_in[0];
    const float* Wp  = (const float*)d_in[2];
    const float* bp  = (const float*)d_in[3];
    const float* Wq  = (const float*)d_in[4];
    const float* bq  = (const float*)d_in[5];
    const float* Wk  = (const float*)d_in[6];
    const float* bk  = (const float*)d_in[7];
    const float* Wv  = (const float*)d_in[8];
    const float* bv  = (const float*)d_in[9];
    const float* Wo  = (const float*)d_in[10];
    const float* bo  = (const float*)d_in[11];
    const float* l1g = (const float*)d_in[12];
    const float* l1b = (const float*)d_in[13];
    const float* W1  = (const float*)d_in[14];
    const float* b1  = (const float*)d_in[15];
    const float* W2  = (const float*)d_in[16];
    const float* b2  = (const float*)d_in[17];
    const float* l2g = (const float*)d_in[18];
    const float* l2b = (const float*)d_in[19];
    const float* Wf  = (const float*)d_in[20];
    const float* bf  = (const float*)d_in[21];
    float* out = (float*)d_out;

    const size_t sm1 = (size_t)(2816 + 256 + 704) * 4;                          /* ~15 KB  */
    const size_t sm2 = (size_t)(10304 + 10240 + 2560) * 4;                      /* ~92 KB  */
    const size_t sm3 = (size_t)(4096 + 16384 + 16384 + 704 + 2048 + 8192 + 8192) * 4; /* ~219 KB */

    cudaFuncSetAttribute(k_qkv,  cudaFuncAttributeMaxDynamicSharedMemorySize, (int)sm1);
    cudaFuncSetAttribute(k_attn, cudaFuncAttributeMaxDynamicSharedMemorySize, (int)sm2);
    cudaFuncSetAttribute(k_epi,  cudaFuncAttributeMaxDynamicSharedMemorySize, (int)sm3);

    k_fold<<<35, 256>>>(Wp, bp, Wq, bq, Wk, bk, Wv, bv);
    k_qkv<<<NROW/64, 512, sm1>>>(inputs, out + OFF_K, out + OFF_V);
    k_attn<<<NPART*4, 256, sm2>>>(out + OFF_K, out + OFF_V, out + OFF_ATTN);
    k_epi<<<148, 512, sm3>>>(Wo, bo, l1g, l1b, W1, b1, W2, b2, l2g, l2b, Wf, bf,
                             out + OFF_R, out + OFF_PRED, out + OFF_PRED2);
}